// round 8
// baseline (speedup 1.0000x reference)
#include <cuda_runtime.h>

#define NB   2
#define SEQ  2048
#define DM   512
#define NH   8
#define HD   64
#define GHD  (NB*NH)      /* 16 global heads */
#define EPSV 1e-8f

typedef unsigned long long u64;

// ---------------- packed f32x2 helpers (FFMA2 only reachable via PTX) ----------------
__device__ __forceinline__ u64 pack2(float lo, float hi) {
    u64 r;
    asm("mov.b64 %0, {%1, %2};" : "=l"(r)
        : "r"(__float_as_uint(lo)), "r"(__float_as_uint(hi)));
    return r;
}
__device__ __forceinline__ void unpack2(u64 v, float& lo, float& hi) {
    unsigned a, b;
    asm("mov.b64 {%0, %1}, %2;" : "=r"(a), "=r"(b) : "l"(v));
    lo = __uint_as_float(a); hi = __uint_as_float(b);
}
__device__ __forceinline__ void fma2(u64& d, u64 a, u64 b) {
    asm("fma.rn.f32x2 %0, %1, %2, %3;" : "=l"(d) : "l"(a), "l"(b), "l"(d));
}

// ---------------- scratch (static device globals: no allocation) ----------------
__device__ float g_Q[GHD*SEQ*HD];
__device__ float g_K[GHD*SEQ*HD];
__device__ float g_V[GHD*SEQ*HD];
__device__ float g_att[NB*SEQ*DM];

// ================= xPos rotary helper =================
__device__ __forceinline__ void rope_pair(float& x1, float& x2, int deven, float pf, bool down)
{
    float sv   = ((float)deven + 25.6f) * (1.0f / 89.6f);
    float invf = powf(10000.0f, -(float)deven * (1.0f / 64.0f));
    float th   = pf * invf;
    float sn, cs;
    sincosf(th, &sn, &cs);
    float sc = powf(sv, pf * (1.0f / 512.0f));
    if (down) sc = 1.0f / sc;
    float y1 = (x1 * cs - x2 * sn) * sc;
    float y2 = (x2 * cs + x1 * sn) * sc;
    x1 = y1; x2 = y2;
}

// ================= Kernel 1: fused QKV projection, 128x128 tiles, 8x8/thread =================
// grid (32 row-blocks, 12 col-blocks of the 1536-wide [Q|K|V] output), 256 threads.
__global__ __launch_bounds__(256) void qkv_kernel(
    const float* __restrict__ X,
    const float* __restrict__ Wq, const float* __restrict__ bq,
    const float* __restrict__ Wk, const float* __restrict__ bk,
    const float* __restrict__ Wv, const float* __restrict__ bv,
    const int*  __restrict__ positions)
{
    __shared__ float Xs[16][132];
    __shared__ float Ws[16][132];

    const int tid = threadIdx.x;
    const int tx  = tid & 15;          // col group: 8 cols at tx*8
    const int ty  = tid >> 4;          // row group: 8 rows at ty*8
    const int r0  = blockIdx.x * 128;
    const int c0  = blockIdx.y * 128;  // 0..1535
    const int kind = c0 / DM;          // 0=Q 1=K 2=V
    const int cW   = c0 % DM;

    const float* W    = (kind == 0) ? Wq : (kind == 1) ? Wk : Wv;
    const float* bias = (kind == 0) ? bq : (kind == 1) ? bk : bv;

    // acc2[i2][j]: row pair (ty*8+2*i2, +1), col tx*8+j
    u64 acc2[4][8];
    #pragma unroll
    for (int i = 0; i < 4; ++i)
        #pragma unroll
        for (int j = 0; j < 8; ++j) acc2[i][j] = 0ull;

    const int lr  = tid >> 1;          // 0..127
    const int lk8 = (tid & 1) * 8;     // 0 or 8

    for (int kb = 0; kb < DM; kb += 16) {
        float4 xa0 = *(const float4*)&X[(size_t)(r0 + lr) * DM + kb + lk8];
        float4 xa1 = *(const float4*)&X[(size_t)(r0 + lr) * DM + kb + lk8 + 4];
        float4 wa0 = *(const float4*)&W[(size_t)(cW + lr) * DM + kb + lk8];
        float4 wa1 = *(const float4*)&W[(size_t)(cW + lr) * DM + kb + lk8 + 4];
        __syncthreads();
        Xs[lk8+0][lr] = xa0.x; Xs[lk8+1][lr] = xa0.y; Xs[lk8+2][lr] = xa0.z; Xs[lk8+3][lr] = xa0.w;
        Xs[lk8+4][lr] = xa1.x; Xs[lk8+5][lr] = xa1.y; Xs[lk8+6][lr] = xa1.z; Xs[lk8+7][lr] = xa1.w;
        Ws[lk8+0][lr] = wa0.x; Ws[lk8+1][lr] = wa0.y; Ws[lk8+2][lr] = wa0.z; Ws[lk8+3][lr] = wa0.w;
        Ws[lk8+4][lr] = wa1.x; Ws[lk8+5][lr] = wa1.y; Ws[lk8+6][lr] = wa1.z; Ws[lk8+7][lr] = wa1.w;
        __syncthreads();

        #pragma unroll
        for (int k = 0; k < 16; ++k) {
            ulonglong2 apA = *(const ulonglong2*)&Xs[k][ty * 8];      // row pairs 0,1
            ulonglong2 apB = *(const ulonglong2*)&Xs[k][ty * 8 + 4];  // row pairs 2,3
            float4 b0 = *(const float4*)&Ws[k][tx * 8];
            float4 b1 = *(const float4*)&Ws[k][tx * 8 + 4];
            u64 bb0 = pack2(b0.x, b0.x), bb1 = pack2(b0.y, b0.y);
            u64 bb2 = pack2(b0.z, b0.z), bb3 = pack2(b0.w, b0.w);
            u64 bb4 = pack2(b1.x, b1.x), bb5 = pack2(b1.y, b1.y);
            u64 bb6 = pack2(b1.z, b1.z), bb7 = pack2(b1.w, b1.w);
            u64 a0 = apA.x, a1 = apA.y, a2 = apB.x, a3 = apB.y;
            fma2(acc2[0][0], a0, bb0); fma2(acc2[0][1], a0, bb1);
            fma2(acc2[0][2], a0, bb2); fma2(acc2[0][3], a0, bb3);
            fma2(acc2[0][4], a0, bb4); fma2(acc2[0][5], a0, bb5);
            fma2(acc2[0][6], a0, bb6); fma2(acc2[0][7], a0, bb7);
            fma2(acc2[1][0], a1, bb0); fma2(acc2[1][1], a1, bb1);
            fma2(acc2[1][2], a1, bb2); fma2(acc2[1][3], a1, bb3);
            fma2(acc2[1][4], a1, bb4); fma2(acc2[1][5], a1, bb5);
            fma2(acc2[1][6], a1, bb6); fma2(acc2[1][7], a1, bb7);
            fma2(acc2[2][0], a2, bb0); fma2(acc2[2][1], a2, bb1);
            fma2(acc2[2][2], a2, bb2); fma2(acc2[2][3], a2, bb3);
            fma2(acc2[2][4], a2, bb4); fma2(acc2[2][5], a2, bb5);
            fma2(acc2[2][6], a2, bb6); fma2(acc2[2][7], a2, bb7);
            fma2(acc2[3][0], a3, bb0); fma2(acc2[3][1], a3, bb1);
            fma2(acc2[3][2], a3, bb2); fma2(acc2[3][3], a3, bb3);
            fma2(acc2[3][4], a3, bb4); fma2(acc2[3][5], a3, bb5);
            fma2(acc2[3][6], a3, bb6); fma2(acc2[3][7], a3, bb7);
        }
    }

    // epilogue: bias (+Q scale) + xPos rotary, store in [head][s][d] layout
    const int h = (cW + tx * 8) / HD;          // global head within 512-block (8 | 64: never crosses)
    const int dbase = (tx * 8) & 63;           // dim within head, multiple of 8
    float* outbuf = (kind == 0) ? g_Q : (kind == 1) ? g_K : g_V;

    float4 bA = *(const float4*)&bias[cW + tx * 8];
    float4 bB = *(const float4*)&bias[cW + tx * 8 + 4];
    float bv8[8] = {bA.x, bA.y, bA.z, bA.w, bB.x, bB.y, bB.z, bB.w};

    #pragma unroll
    for (int i2 = 0; i2 < 4; ++i2) {
        float rl[8], rh[8];
        #pragma unroll
        for (int j = 0; j < 8; ++j) unpack2(acc2[i2][j], rl[j], rh[j]);
        #pragma unroll
        for (int half = 0; half < 2; ++half) {
            float* v = half ? rh : rl;
            int r = r0 + ty * 8 + 2 * i2 + half;
            int n = r >> 11, s = r & 2047;
            float o[8];
            #pragma unroll
            for (int j = 0; j < 8; ++j) o[j] = v[j] + bv8[j];
            if (kind != 2) {
                if (kind == 0) {
                    #pragma unroll
                    for (int j = 0; j < 8; ++j) o[j] *= 0.125f;
                }
                float pf = (float)positions[r];
                bool down = (kind == 1);
                #pragma unroll
                for (int j2 = 0; j2 < 4; ++j2)
                    rope_pair(o[2*j2], o[2*j2+1], dbase + 2*j2, pf, down);
            }
            float* dst = outbuf + ((size_t)(n * NH + h) * SEQ + s) * HD + dbase;
            *(float4*)dst       = make_float4(o[0], o[1], o[2], o[3]);
            *(float4*)(dst + 4) = make_float4(o[4], o[5], o[6], o[7]);
        }
    }
}

// ================= Kernel 2: fused attention (sigmoid + suffix-product gating + AV) =================
// smem: QS/KS/VS/AS [64][68] floats + ASd [64][66] float2 + WB/MS
#define ATTN_SMEM ((4*64*68 + 2*64*66 + 2*64) * 4)

__global__ __launch_bounds__(256, 2) void attn_kernel(const float* __restrict__ mask)
{
    extern __shared__ float sm[];
    float*  QS  = sm;                       // [64][68]
    float*  KS  = QS + 64 * 68;             // [64][68]
    float*  VS  = KS + 64 * 68;             // [64][68]
    float*  AS  = VS + 64 * 68;             // row-major sigmoid output [64][68]
    float2* ASd = (float2*)(AS + 64 * 68);  // duplicated weights [col t][row r], stride 66
    float*  WB  = (float*)(ASd + 64 * 66);  // boundary weights (64)
    float*  MS  = WB + 64;                  // input_mask tile (64)

    const int tid = threadIdx.x;
    const int tx  = tid & 15;
    const int ty  = tid >> 4;
    const int sr  = tid >> 2;               // scan row 0..63
    const int sq  = tid & 3;                // scan segment 0..3 (cols 16sq..16sq+15)
    const int gh  = blockIdx.y;
    const int n   = gh >> 3;
    const int rb  = (int)(gridDim.x - 1 - blockIdx.x);   // heavy blocks launch first
    const int s0  = rb * 64;

    const float* Qg = g_Q + (size_t)gh * SEQ * HD;
    const float* Kg = g_K + (size_t)gh * SEQ * HD;
    const float* Vg = g_V + (size_t)gh * SEQ * HD;

    // load Q tile
    for (int it = tid; it < 64 * 16; it += 256) {
        int rr = it >> 4, f4 = it & 15;
        *(float4*)&QS[rr * 68 + f4 * 4] = *(const float4*)&Qg[(size_t)(s0 + rr) * HD + f4 * 4];
    }

    // per-row scan carries (identical across the 4 threads of a row)
    float cA = 0.0f;
    float cP = 1.0f;
    float4 vb_prev = make_float4(0.f, 0.f, 0.f, 0.f);   // V row 0 of previously processed tile

    // out2[i][j2]: row ty*4+i, col pair (tx*4+2*j2, +1)
    u64 out2[4][2];
    #pragma unroll
    for (int i = 0; i < 4; ++i) { out2[i][0] = 0ull; out2[i][1] = 0ull; }

    __syncthreads();

    for (int jb = rb; jb >= 0; --jb) {
        const int lo = jb * 64;

        for (int it = tid; it < 64 * 16; it += 256) {
            int rr = it >> 4, f4 = it & 15;
            *(float4*)&KS[rr * 68 + f4 * 4] = *(const float4*)&Kg[(size_t)(lo + rr) * HD + f4 * 4];
            *(float4*)&VS[rr * 68 + f4 * 4] = *(const float4*)&Vg[(size_t)(lo + rr) * HD + f4 * 4];
        }
        if (tid < 64) MS[tid] = mask[n * SEQ + lo + tid];
        __syncthreads();                               // (a)

        // ---- S = Q K^T (64x64x64), packed along d ----
        u64 acc2[4][4];
        #pragma unroll
        for (int i = 0; i < 4; ++i)
            #pragma unroll
            for (int j = 0; j < 4; ++j) acc2[i][j] = 0ull;

        #pragma unroll 4
        for (int d = 0; d < 64; d += 4) {
            ulonglong2 qa[4], kb[4];
            #pragma unroll
            for (int i = 0; i < 4; ++i) qa[i] = *(const ulonglong2*)&QS[(ty * 4 + i) * 68 + d];
            #pragma unroll
            for (int j = 0; j < 4; ++j) kb[j] = *(const ulonglong2*)&KS[(tx * 4 + j) * 68 + d];
            #pragma unroll
            for (int i = 0; i < 4; ++i)
                #pragma unroll
                for (int j = 0; j < 4; ++j) {
                    fma2(acc2[i][j], qa[i].x, kb[j].x);
                    fma2(acc2[i][j], qa[i].y, kb[j].y);
                }
        }
        float sa[4][4];
        #pragma unroll
        for (int i = 0; i < 4; ++i)
            #pragma unroll
            for (int j = 0; j < 4; ++j) {
                float l, h; unpack2(acc2[i][j], l, h);
                sa[i][j] = l + h;
            }

        // ---- A = sigmoid(S) * mask * causal, row-major store ----
        {
            float m0 = MS[tx*4+0], m1 = MS[tx*4+1], m2 = MS[tx*4+2], m3 = MS[tx*4+3];
            #pragma unroll
            for (int i = 0; i < 4; ++i) {
                int sg = s0 + ty * 4 + i;
                float4 w4;
                w4.x = (lo + tx*4 + 0 <= sg) ? __fdividef(m0, 1.0f + __expf(-sa[i][0])) : 0.0f;
                w4.y = (lo + tx*4 + 1 <= sg) ? __fdividef(m1, 1.0f + __expf(-sa[i][1])) : 0.0f;
                w4.z = (lo + tx*4 + 2 <= sg) ? __fdividef(m2, 1.0f + __expf(-sa[i][2])) : 0.0f;
                w4.w = (lo + tx*4 + 3 <= sg) ? __fdividef(m3, 1.0f + __expf(-sa[i][3])) : 0.0f;
                *(float4*)&AS[(ty * 4 + i) * 68 + tx * 4] = w4;
            }
        }
        __syncthreads();                               // (b)

        // ---- parallel suffix-product scan: 4 threads per row, 16 cols each ----
        {
            float a[16];
            float4 f0 = *(const float4*)&AS[sr * 68 + sq * 16 + 0];
            float4 f1 = *(const float4*)&AS[sr * 68 + sq * 16 + 4];
            float4 f2 = *(const float4*)&AS[sr * 68 + sq * 16 + 8];
            float4 f3 = *(const float4*)&AS[sr * 68 + sq * 16 + 12];
            a[0]=f0.x; a[1]=f0.y; a[2]=f0.z; a[3]=f0.w;
            a[4]=f1.x; a[5]=f1.y; a[6]=f1.z; a[7]=f1.w;
            a[8]=f2.x; a[9]=f2.y; a[10]=f2.z; a[11]=f2.w;
            a[12]=f3.x; a[13]=f3.y; a[14]=f3.z; a[15]=f3.w;

            float pp = 1.0f;
            #pragma unroll
            for (int i = 15; i >= 0; --i) pp *= (1.0f - a[i]) + EPSV;

            float p0 = __shfl_sync(0xffffffffu, pp, 0, 4);
            float p1 = __shfl_sync(0xffffffffu, pp, 1, 4);
            float p2 = __shfl_sync(0xffffffffu, pp, 2, 4);
            float p3 = __shfl_sync(0xffffffffu, pp, 3, 4);
            float aN = __shfl_down_sync(0xffffffffu, a[0], 1, 4);  // a_low of next segment

            float lA = (sq == 3) ? cA : aN;
            float lP = cP;
            if (sq < 3) lP *= p3;
            if (sq < 2) lP *= p2;
            if (sq < 1) lP *= p1;

            #pragma unroll
            for (int i = 15; i >= 0; --i) {
                float Pn = ((1.0f - a[i]) + EPSV) * lP;
                float w  = lA * Pn;
                int t = sq * 16 + i + 1;
                if (t == 64) WB[sr] = w;
                else         ASd[t * 66 + sr] = make_float2(w, w);
                lA = a[i]; lP = Pn;
            }
            if (sq == 0) {
                float w0 = (jb == 0) ? a[0] : 0.0f;
                ASd[sr] = make_float2(w0, w0);
            }
            cP = cP * p3 * p2 * p1 * p0;
            cA = __shfl_sync(0xffffffffu, a[0], 0, 4);
        }
        __syncthreads();                               // (c)

        // ---- out += W_tile * V_tile ----
        #pragma unroll 8
        for (int c = 0; c < 64; ++c) {
            const float2* wrow = &ASd[c * 66 + ty * 4];
            ulonglong2 wA = *(const ulonglong2*)wrow;        // (w0,w0),(w1,w1)
            ulonglong2 wC = *(const ulonglong2*)(wrow + 2);  // (w2,w2),(w3,w3)
            ulonglong2 vv = *(const ulonglong2*)&VS[c * 68 + tx * 4];  // (v0,v1),(v2,v3)
            fma2(out2[0][0], wA.x, vv.x); fma2(out2[0][1], wA.x, vv.y);
            fma2(out2[1][0], wA.y, vv.x); fma2(out2[1][1], wA.y, vv.y);
            fma2(out2[2][0], wC.x, vv.x); fma2(out2[2][1], wC.x, vv.y);
            fma2(out2[3][0], wC.y, vv.x); fma2(out2[3][1], wC.y, vv.y);
        }
        // boundary column: weight WB (this scan) x V row 0 of PREVIOUS tile (registers)
        {
            u64 vbx = pack2(vb_prev.x, vb_prev.y);
            u64 vby = pack2(vb_prev.z, vb_prev.w);
            #pragma unroll
            for (int i = 0; i < 4; ++i) {
                float wv = WB[ty * 4 + i];
                u64 wd = pack2(wv, wv);
                fma2(out2[i][0], wd, vbx);
                fma2(out2[i][1], wd, vby);
            }
        }
        // capture V row 0 of THIS tile for the next iteration's boundary term
        vb_prev = *(const float4*)&VS[0 * 68 + tx * 4];
        __syncthreads();                               // (d) protect smem for next load
    }

    // write attended in (N, S, H*64) layout for the output projection
    const int h = gh & 7;
    #pragma unroll
    for (int i = 0; i < 4; ++i) {
        float o0, o1, o2, o3;
        unpack2(out2[i][0], o0, o1);
        unpack2(out2[i][1], o2, o3);
        int s = s0 + ty * 4 + i;
        float* dst = g_att + ((size_t)(n * SEQ + s)) * DM + h * HD + tx * 4;
        *(float4*)dst = make_float4(o0, o1, o2, o3);
    }
}

// ================= Kernel 3: output projection, 128x128 tiles, 8x8/thread =================
__global__ __launch_bounds__(256) void oproj_kernel(
    const float* __restrict__ Wo, const float* __restrict__ bo,
    float* __restrict__ outp)
{
    __shared__ float Xs[16][132];
    __shared__ float Ws[16][132];

    const int tid = threadIdx.x;
    const int tx  = tid & 15;
    const int ty  = tid >> 4;
    const int r0  = blockIdx.x * 128;
    const int c0  = blockIdx.y * 128;

    u64 acc2[4][8];
    #pragma unroll
    for (int i = 0; i < 4; ++i)
        #pragma unroll
        for (int j = 0; j < 8; ++j) acc2[i][j] = 0ull;

    const int lr  = tid >> 1;
    const int lk8 = (tid & 1) * 8;

    for (int kb = 0; kb < DM; kb += 16) {
        float4 xa0 = *(const float4*)&g_att[(size_t)(r0 + lr) * DM + kb + lk8];
        float4 xa1 = *(const float4*)&g_att[(size_t)(r0 + lr) * DM + kb + lk8 + 4];
        float4 wa0 = *(const float4*)&Wo[(size_t)(c0 + lr) * DM + kb + lk8];
        float4 wa1 = *(const float4*)&Wo[(size_t)(c0 + lr) * DM + kb + lk8 + 4];
        __syncthreads();
        Xs[lk8+0][lr] = xa0.x; Xs[lk8+1][lr] = xa0.y; Xs[lk8+2][lr] = xa0.z; Xs[lk8+3][lr] = xa0.w;
        Xs[lk8+4][lr] = xa1.x; Xs[lk8+5][lr] = xa1.y; Xs[lk8+6][lr] = xa1.z; Xs[lk8+7][lr] = xa1.w;
        Ws[lk8+0][lr] = wa0.x; Ws[lk8+1][lr] = wa0.y; Ws[lk8+2][lr] = wa0.z; Ws[lk8+3][lr] = wa0.w;
        Ws[lk8+4][lr] = wa1.x; Ws[lk8+5][lr] = wa1.y; Ws[lk8+6][lr] = wa1.z; Ws[lk8+7][lr] = wa1.w;
        __syncthreads();

        #pragma unroll
        for (int k = 0; k < 16; ++k) {
            ulonglong2 apA = *(const ulonglong2*)&Xs[k][ty * 8];
            ulonglong2 apB = *(const ulonglong2*)&Xs[k][ty * 8 + 4];
            float4 b0 = *(const float4*)&Ws[k][tx * 8];
            float4 b1 = *(const float4*)&Ws[k][tx * 8 + 4];
            u64 bb0 = pack2(b0.x, b0.x), bb1 = pack2(b0.y, b0.y);
            u64 bb2 = pack2(b0.z, b0.z), bb3 = pack2(b0.w, b0.w);
            u64 bb4 = pack2(b1.x, b1.x), bb5 = pack2(b1.y, b1.y);
            u64 bb6 = pack2(b1.z, b1.z), bb7 = pack2(b1.w, b1.w);
            u64 a0 = apA.x, a1 = apA.y, a2 = apB.x, a3 = apB.y;
            fma2(acc2[0][0], a0, bb0); fma2(acc2[0][1], a0, bb1);
            fma2(acc2[0][2], a0, bb2); fma2(acc2[0][3], a0, bb3);
            fma2(acc2[0][4], a0, bb4); fma2(acc2[0][5], a0, bb5);
            fma2(acc2[0][6], a0, bb6); fma2(acc2[0][7], a0, bb7);
            fma2(acc2[1][0], a1, bb0); fma2(acc2[1][1], a1, bb1);
            fma2(acc2[1][2], a1, bb2); fma2(acc2[1][3], a1, bb3);
            fma2(acc2[1][4], a1, bb4); fma2(acc2[1][5], a1, bb5);
            fma2(acc2[1][6], a1, bb6); fma2(acc2[1][7], a1, bb7);
            fma2(acc2[2][0], a2, bb0); fma2(acc2[2][1], a2, bb1);
            fma2(acc2[2][2], a2, bb2); fma2(acc2[2][3], a2, bb3);
            fma2(acc2[2][4], a2, bb4); fma2(acc2[2][5], a2, bb5);
            fma2(acc2[2][6], a2, bb6); fma2(acc2[2][7], a2, bb7);
            fma2(acc2[3][0], a3, bb0); fma2(acc2[3][1], a3, bb1);
            fma2(acc2[3][2], a3, bb2); fma2(acc2[3][3], a3, bb3);
            fma2(acc2[3][4], a3, bb4); fma2(acc2[3][5], a3, bb5);
            fma2(acc2[3][6], a3, bb6); fma2(acc2[3][7], a3, bb7);
        }
    }

    float4 bA = *(const float4*)&bo[c0 + tx * 8];
    float4 bB = *(const float4*)&bo[c0 + tx * 8 + 4];
    float bv8[8] = {bA.x, bA.y, bA.z, bA.w, bB.x, bB.y, bB.z, bB.w};

    #pragma unroll
    for (int i2 = 0; i2 < 4; ++i2) {
        float rl[8], rh[8];
        #pragma unroll
        for (int j = 0; j < 8; ++j) unpack2(acc2[i2][j], rl[j], rh[j]);
        #pragma unroll
        for (int half = 0; half < 2; ++half) {
            float* v = half ? rh : rl;
            int r = r0 + ty * 8 + 2 * i2 + half;
            float* dst = &outp[(size_t)r * DM + c0 + tx * 8];
            *(float4*)dst       = make_float4(v[0]+bv8[0], v[1]+bv8[1], v[2]+bv8[2], v[3]+bv8[3]);
            *(float4*)(dst + 4) = make_float4(v[4]+bv8[4], v[5]+bv8[5], v[6]+bv8[6], v[7]+bv8[7]);
        }
    }
}

// ================= host launcher =================
extern "C" void kernel_launch(void* const* d_in, const int* in_sizes, int n_in,
                              void* d_out, int out_size)
{
    const float* seqp = nullptr;
    const float* maskp = nullptr;
    const int*   posp = nullptr;
    const float* W[4] = {nullptr, nullptr, nullptr, nullptr};
    const float* B[4] = {nullptr, nullptr, nullptr, nullptr};
    int nw = 0, nb = 0, n4096 = 0;
    for (int i = 0; i < n_in; ++i) {
        int sz = in_sizes[i];
        if (sz == NB * SEQ * DM) {
            seqp = (const float*)d_in[i];
        } else if (sz == DM * DM) {
            if (nw < 4) W[nw++] = (const float*)d_in[i];
        } else if (sz == DM) {
            if (nb < 4) B[nb++] = (const float*)d_in[i];
        } else if (sz == NB * SEQ) {
            if (n4096 == 0) maskp = (const float*)d_in[i];
            else            posp  = (const int*)d_in[i];
            ++n4096;
        }
    }

    cudaFuncSetAttribute(attn_kernel, cudaFuncAttributeMaxDynamicSharedMemorySize, ATTN_SMEM);

    qkv_kernel<<<dim3(32, 12), 256>>>(seqp, W[0], B[0], W[1], B[1], W[2], B[2], posp);
    attn_kernel<<<dim3(32, 16), 256, ATTN_SMEM>>>(maskp);
    oproj_kernel<<<dim3(32, 4), 256>>>(W[3], B[3], (float*)d_out);
}

// round 9
// speedup vs baseline: 1.5575x; 1.5575x over previous
#include <cuda_runtime.h>

#define NB   2
#define SEQ  2048
#define DM   512
#define NH   8
#define HD   64
#define GHD  (NB*NH)      /* 16 global heads */
#define EPSV 1e-8f

typedef unsigned long long u64;

// ---------------- packed f32x2 helpers (FFMA2 only reachable via PTX) ----------------
__device__ __forceinline__ u64 pack2(float lo, float hi) {
    u64 r;
    asm("mov.b64 %0, {%1, %2};" : "=l"(r)
        : "r"(__float_as_uint(lo)), "r"(__float_as_uint(hi)));
    return r;
}
__device__ __forceinline__ void unpack2(u64 v, float& lo, float& hi) {
    unsigned a, b;
    asm("mov.b64 {%0, %1}, %2;" : "=r"(a), "=r"(b) : "l"(v));
    lo = __uint_as_float(a); hi = __uint_as_float(b);
}
__device__ __forceinline__ void fma2(u64& d, u64 a, u64 b) {
    asm("fma.rn.f32x2 %0, %1, %2, %3;" : "=l"(d) : "l"(a), "l"(b), "l"(d));
}

// ---------------- scratch (static device globals: no allocation) ----------------
__device__ float g_Q[GHD*SEQ*HD];
__device__ float g_K[GHD*SEQ*HD];
__device__ float g_V[GHD*SEQ*HD];
__device__ float g_att[NB*SEQ*DM];

// ================= xPos rotary helper =================
__device__ __forceinline__ void rope_pair(float& x1, float& x2, int deven, float pf, bool down)
{
    float sv   = ((float)deven + 25.6f) * (1.0f / 89.6f);
    float invf = powf(10000.0f, -(float)deven * (1.0f / 64.0f));
    float th   = pf * invf;
    float sn, cs;
    sincosf(th, &sn, &cs);
    float sc = powf(sv, pf * (1.0f / 512.0f));
    if (down) sc = 1.0f / sc;
    float y1 = (x1 * cs - x2 * sn) * sc;
    float y2 = (x2 * cs + x1 * sn) * sc;
    x1 = y1; x2 = y2;
}

// ================= Kernel 1: fused QKV projection (R7 revert: 64x64 tile, 4x4/thread) =================
__global__ __launch_bounds__(256) void qkv_kernel(
    const float* __restrict__ X,
    const float* __restrict__ Wq, const float* __restrict__ bq,
    const float* __restrict__ Wk, const float* __restrict__ bk,
    const float* __restrict__ Wv, const float* __restrict__ bv,
    const int*  __restrict__ positions)
{
    __shared__ float Xs[16][68];
    __shared__ float Ws[16][68];

    const int tid = threadIdx.x;
    const int tx  = tid & 15;
    const int ty  = tid >> 4;
    const int r0  = blockIdx.x * 64;
    const int c0  = blockIdx.y * 64;          // 0..1535
    const int kind = c0 / DM;                  // 0=Q 1=K 2=V
    const int cW   = c0 % DM;

    const float* W    = (kind == 0) ? Wq : (kind == 1) ? Wk : Wv;
    const float* bias = (kind == 0) ? bq : (kind == 1) ? bk : bv;

    u64 acc2[2][4];
    #pragma unroll
    for (int i = 0; i < 2; ++i)
        #pragma unroll
        for (int j = 0; j < 4; ++j) acc2[i][j] = 0ull;

    const int lr = tid >> 2;      // 0..63
    const int lk = tid & 3;       // float4 index within 16-wide K chunk

    for (int kb = 0; kb < DM; kb += 16) {
        float4 xa = *(const float4*)&X[(size_t)(r0 + lr) * DM + kb + lk * 4];
        float4 wa = *(const float4*)&W[(size_t)(cW + lr) * DM + kb + lk * 4];
        Xs[lk*4+0][lr] = xa.x; Xs[lk*4+1][lr] = xa.y; Xs[lk*4+2][lr] = xa.z; Xs[lk*4+3][lr] = xa.w;
        Ws[lk*4+0][lr] = wa.x; Ws[lk*4+1][lr] = wa.y; Ws[lk*4+2][lr] = wa.z; Ws[lk*4+3][lr] = wa.w;
        __syncthreads();

        #pragma unroll
        for (int k = 0; k < 16; ++k) {
            ulonglong2 ap = *(const ulonglong2*)&Xs[k][ty * 4];  // (a0,a1),(a2,a3)
            float4 b = *(const float4*)&Ws[k][tx * 4];
            u64 b0 = pack2(b.x, b.x), b1 = pack2(b.y, b.y);
            u64 b2 = pack2(b.z, b.z), b3 = pack2(b.w, b.w);
            fma2(acc2[0][0], ap.x, b0); fma2(acc2[0][1], ap.x, b1);
            fma2(acc2[0][2], ap.x, b2); fma2(acc2[0][3], ap.x, b3);
            fma2(acc2[1][0], ap.y, b0); fma2(acc2[1][1], ap.y, b1);
            fma2(acc2[1][2], ap.y, b2); fma2(acc2[1][3], ap.y, b3);
        }
        __syncthreads();
    }

    float acc[4][4];
    #pragma unroll
    for (int i2 = 0; i2 < 2; ++i2)
        #pragma unroll
        for (int j = 0; j < 4; ++j)
            unpack2(acc2[i2][j], acc[2*i2][j], acc[2*i2+1][j]);

    const int h = cW / HD;
    const int dbase = tx * 4;
    float* outbuf = (kind == 0) ? g_Q : (kind == 1) ? g_K : g_V;

    #pragma unroll
    for (int i = 0; i < 4; ++i) {
        int r = r0 + ty * 4 + i;
        int n = r >> 11, s = r & 2047;
        float v0 = acc[i][0] + bias[cW + dbase + 0];
        float v1 = acc[i][1] + bias[cW + dbase + 1];
        float v2 = acc[i][2] + bias[cW + dbase + 2];
        float v3 = acc[i][3] + bias[cW + dbase + 3];
        if (kind != 2) {
            if (kind == 0) { v0 *= 0.125f; v1 *= 0.125f; v2 *= 0.125f; v3 *= 0.125f; }
            float pf = (float)positions[r];
            bool down = (kind == 1);
            rope_pair(v0, v1, dbase + 0, pf, down);
            rope_pair(v2, v3, dbase + 2, pf, down);
        }
        float* dst = outbuf + ((size_t)(n * NH + h) * SEQ + s) * HD + dbase;
        *(float4*)dst = make_float4(v0, v1, v2, v3);
    }
}

// ================= Kernel 2: fused attention =================
// smem: QS/KS/VS/ASt [64][68] floats + ASd [64][66] float2 + WB/MS
#define ATTN_SMEM ((4*64*68 + 2*64*66 + 2*64) * 4)

__global__ __launch_bounds__(256, 2) void attn_kernel(const float* __restrict__ mask)
{
    extern __shared__ float sm[];
    float*  QS  = sm;                        // [64][68]
    float*  KS  = QS + 64 * 68;              // [64][68]
    float*  VS  = KS + 64 * 68;              // [64][68]
    float*  ASt = VS + 64 * 68;              // transposed sigmoid A [col][row], stride 68
    float2* ASd = (float2*)(ASt + 64 * 68);  // duplicated weights [col t][row r], stride 66
    float*  WB  = (float*)(ASd + 64 * 66);   // boundary weights (64)
    float*  MS  = WB + 64;                   // input_mask tile (64)

    const int tid = threadIdx.x;
    const int tx  = tid & 15;
    const int ty  = tid >> 4;
    const int gh  = blockIdx.y;
    const int n   = gh >> 3;
    const int rb  = (int)(gridDim.x - 1 - blockIdx.x);   // heavy blocks launch first
    const int s0  = rb * 64;

    const float* Qg = g_Q + (size_t)gh * SEQ * HD;
    const float* Kg = g_K + (size_t)gh * SEQ * HD;
    const float* Vg = g_V + (size_t)gh * SEQ * HD;

    // load Q tile
    for (int it = tid; it < 64 * 16; it += 256) {
        int rr = it >> 4, f4 = it & 15;
        *(float4*)&QS[rr * 68 + f4 * 4] = *(const float4*)&Qg[(size_t)(s0 + rr) * HD + f4 * 4];
    }

    // per-row scan carries (threads 0..63 own row tid)
    float cA = 0.0f;
    float cP = 1.0f;
    float4 vb_prev = make_float4(0.f, 0.f, 0.f, 0.f);   // V row 0 of previously processed tile

    // out2[i][j2]: row ty*4+i, col pair (tx*4+2*j2, +1)
    u64 out2[4][2];
    #pragma unroll
    for (int i = 0; i < 4; ++i) { out2[i][0] = 0ull; out2[i][1] = 0ull; }

    // ---- register prefetch of first K/V tile + mask ----
    float4 kreg[4], vreg[4];
    float  mreg = 0.0f;
    {
        const int lo = rb * 64;
        #pragma unroll
        for (int q = 0; q < 4; ++q) {
            int idx = tid + q * 256;
            int rr = idx >> 4, f4 = idx & 15;
            kreg[q] = *(const float4*)&Kg[(size_t)(lo + rr) * HD + f4 * 4];
            vreg[q] = *(const float4*)&Vg[(size_t)(lo + rr) * HD + f4 * 4];
        }
        if (tid < 64) mreg = mask[n * SEQ + lo + tid];
    }

    for (int jb = rb; jb >= 0; --jb) {
        // commit prefetched tile to smem
        #pragma unroll
        for (int q = 0; q < 4; ++q) {
            int idx = tid + q * 256;
            int rr = idx >> 4, f4 = idx & 15;
            *(float4*)&KS[rr * 68 + f4 * 4] = kreg[q];
            *(float4*)&VS[rr * 68 + f4 * 4] = vreg[q];
        }
        if (tid < 64) MS[tid] = mreg;
        __syncthreads();                               // (a)

        // issue prefetch for next tile (latency hidden behind this tile's compute)
        if (jb > 0) {
            const int lo2 = (jb - 1) * 64;
            #pragma unroll
            for (int q = 0; q < 4; ++q) {
                int idx = tid + q * 256;
                int rr = idx >> 4, f4 = idx & 15;
                kreg[q] = *(const float4*)&Kg[(size_t)(lo2 + rr) * HD + f4 * 4];
                vreg[q] = *(const float4*)&Vg[(size_t)(lo2 + rr) * HD + f4 * 4];
            }
            if (tid < 64) mreg = mask[n * SEQ + lo2 + tid];
        }

        const int lo = jb * 64;

        // ---- S = Q K^T (64x64x64), packed along d ----
        u64 acc2[4][4];
        #pragma unroll
        for (int i = 0; i < 4; ++i)
            #pragma unroll
            for (int j = 0; j < 4; ++j) acc2[i][j] = 0ull;

        #pragma unroll 4
        for (int d = 0; d < 64; d += 4) {
            ulonglong2 qa[4], kb[4];
            #pragma unroll
            for (int i = 0; i < 4; ++i) qa[i] = *(const ulonglong2*)&QS[(ty * 4 + i) * 68 + d];
            #pragma unroll
            for (int j = 0; j < 4; ++j) kb[j] = *(const ulonglong2*)&KS[(tx * 4 + j) * 68 + d];
            #pragma unroll
            for (int i = 0; i < 4; ++i)
                #pragma unroll
                for (int j = 0; j < 4; ++j) {
                    fma2(acc2[i][j], qa[i].x, kb[j].x);
                    fma2(acc2[i][j], qa[i].y, kb[j].y);
                }
        }
        float sa[4][4];
        #pragma unroll
        for (int i = 0; i < 4; ++i)
            #pragma unroll
            for (int j = 0; j < 4; ++j) {
                float l, h; unpack2(acc2[i][j], l, h);
                sa[i][j] = l + h;
            }

        // ---- A = sigmoid(S) * mask * causal, stored TRANSPOSED: ASt[c][r] ----
        #pragma unroll
        for (int j = 0; j < 4; ++j) {
            int tg = lo + tx * 4 + j;
            float mj = MS[tx * 4 + j];
            float w4[4];
            #pragma unroll
            for (int i = 0; i < 4; ++i) {
                int sg = s0 + ty * 4 + i;
                float a = 0.0f;
                if (tg <= sg)
                    a = __fdividef(mj, 1.0f + __expf(-sa[i][j]));
                w4[i] = a;
            }
            *(float4*)&ASt[(tx * 4 + j) * 68 + ty * 4] = make_float4(w4[0], w4[1], w4[2], w4[3]);
        }
        __syncthreads();                               // (b)

        // ---- per-row serial suffix-product scan (R7-proven), writes duplicated weights ----
        if (tid < 64) {
            const int r = tid;
            float lA = cA, lP = cP;
            for (int c = 63; c >= 0; --c) {
                float a  = ASt[c * 68 + r];
                float Pn = ((1.0f - a) + EPSV) * lP;
                float w  = lA * Pn;
                if (c == 63) WB[r] = w;
                else         ASd[(c + 1) * 66 + r] = make_float2(w, w);
                lA = a; lP = Pn;
            }
            float w0 = (jb == 0) ? lA : 0.0f;
            ASd[r] = make_float2(w0, w0);
            cA = lA; cP = lP;
        }
        __syncthreads();                               // (c)

        // ---- out += W_tile * V_tile (duplicated weights: no pack movs) ----
        #pragma unroll 8
        for (int c = 0; c < 64; ++c) {
            const float2* wrow = &ASd[c * 66 + ty * 4];
            ulonglong2 wA = *(const ulonglong2*)wrow;        // (w0,w0),(w1,w1)
            ulonglong2 wC = *(const ulonglong2*)(wrow + 2);  // (w2,w2),(w3,w3)
            ulonglong2 vv = *(const ulonglong2*)&VS[c * 68 + tx * 4];  // (v0,v1),(v2,v3)
            fma2(out2[0][0], wA.x, vv.x); fma2(out2[0][1], wA.x, vv.y);
            fma2(out2[1][0], wA.y, vv.x); fma2(out2[1][1], wA.y, vv.y);
            fma2(out2[2][0], wC.x, vv.x); fma2(out2[2][1], wC.x, vv.y);
            fma2(out2[3][0], wC.y, vv.x); fma2(out2[3][1], wC.y, vv.y);
        }
        // boundary column: weight WB (this scan) x V row 0 of PREVIOUS tile (registers)
        {
            u64 vbx = pack2(vb_prev.x, vb_prev.y);
            u64 vby = pack2(vb_prev.z, vb_prev.w);
            #pragma unroll
            for (int i = 0; i < 4; ++i) {
                float wv = WB[ty * 4 + i];
                u64 wd = pack2(wv, wv);
                fma2(out2[i][0], wd, vbx);
                fma2(out2[i][1], wd, vby);
            }
        }
        // capture V row 0 of THIS tile before smem is recycled
        vb_prev = *(const float4*)&VS[0 * 68 + tx * 4];
        __syncthreads();                               // (d)
    }

    // write attended in (N, S, H*64) layout for the output projection
    const int h = gh & 7;
    #pragma unroll
    for (int i = 0; i < 4; ++i) {
        float o0, o1, o2, o3;
        unpack2(out2[i][0], o0, o1);
        unpack2(out2[i][1], o2, o3);
        int s = s0 + ty * 4 + i;
        float* dst = g_att + ((size_t)(n * SEQ + s)) * DM + h * HD + tx * 4;
        *(float4*)dst = make_float4(o0, o1, o2, o3);
    }
}

// ================= Kernel 3: output projection (R7 revert) =================
__global__ __launch_bounds__(256) void oproj_kernel(
    const float* __restrict__ Wo, const float* __restrict__ bo,
    float* __restrict__ outp)
{
    __shared__ float Xs[16][68];
    __shared__ float Ws[16][68];

    const int tid = threadIdx.x;
    const int tx  = tid & 15;
    const int ty  = tid >> 4;
    const int r0  = blockIdx.x * 64;
    const int c0  = blockIdx.y * 64;

    u64 acc2[2][4];
    #pragma unroll
    for (int i = 0; i < 2; ++i)
        #pragma unroll
        for (int j = 0; j < 4; ++j) acc2[i][j] = 0ull;

    const int lr = tid >> 2;
    const int lk = tid & 3;

    for (int kb = 0; kb < DM; kb += 16) {
        float4 xa = *(const float4*)&g_att[(size_t)(r0 + lr) * DM + kb + lk * 4];
        float4 wa = *(const float4*)&Wo[(size_t)(c0 + lr) * DM + kb + lk * 4];
        Xs[lk*4+0][lr] = xa.x; Xs[lk*4+1][lr] = xa.y; Xs[lk*4+2][lr] = xa.z; Xs[lk*4+3][lr] = xa.w;
        Ws[lk*4+0][lr] = wa.x; Ws[lk*4+1][lr] = wa.y; Ws[lk*4+2][lr] = wa.z; Ws[lk*4+3][lr] = wa.w;
        __syncthreads();

        #pragma unroll
        for (int k = 0; k < 16; ++k) {
            ulonglong2 ap = *(const ulonglong2*)&Xs[k][ty * 4];
            float4 b = *(const float4*)&Ws[k][tx * 4];
            u64 b0 = pack2(b.x, b.x), b1 = pack2(b.y, b.y);
            u64 b2 = pack2(b.z, b.z), b3 = pack2(b.w, b.w);
            fma2(acc2[0][0], ap.x, b0); fma2(acc2[0][1], ap.x, b1);
            fma2(acc2[0][2], ap.x, b2); fma2(acc2[0][3], ap.x, b3);
            fma2(acc2[1][0], ap.y, b0); fma2(acc2[1][1], ap.y, b1);
            fma2(acc2[1][2], ap.y, b2); fma2(acc2[1][3], ap.y, b3);
        }
        __syncthreads();
    }

    float acc[4][4];
    #pragma unroll
    for (int i2 = 0; i2 < 2; ++i2)
        #pragma unroll
        for (int j = 0; j < 4; ++j)
            unpack2(acc2[i2][j], acc[2*i2][j], acc[2*i2+1][j]);

    #pragma unroll
    for (int i = 0; i < 4; ++i) {
        int r = r0 + ty * 4 + i;
        float b0 = bo[c0 + tx * 4 + 0];
        float b1 = bo[c0 + tx * 4 + 1];
        float b2 = bo[c0 + tx * 4 + 2];
        float b3 = bo[c0 + tx * 4 + 3];
        *(float4*)&outp[(size_t)r * DM + c0 + tx * 4] =
            make_float4(acc[i][0] + b0, acc[i][1] + b1, acc[i][2] + b2, acc[i][3] + b3);
    }
}

// ================= host launcher =================
extern "C" void kernel_launch(void* const* d_in, const int* in_sizes, int n_in,
                              void* d_out, int out_size)
{
    const float* seqp = nullptr;
    const float* maskp = nullptr;
    const int*   posp = nullptr;
    const float* W[4] = {nullptr, nullptr, nullptr, nullptr};
    const float* B[4] = {nullptr, nullptr, nullptr, nullptr};
    int nw = 0, nb = 0, n4096 = 0;
    for (int i = 0; i < n_in; ++i) {
        int sz = in_sizes[i];
        if (sz == NB * SEQ * DM) {
            seqp = (const float*)d_in[i];
        } else if (sz == DM * DM) {
            if (nw < 4) W[nw++] = (const float*)d_in[i];
        } else if (sz == DM) {
            if (nb < 4) B[nb++] = (const float*)d_in[i];
        } else if (sz == NB * SEQ) {
            if (n4096 == 0) maskp = (const float*)d_in[i];
            else            posp  = (const int*)d_in[i];
            ++n4096;
        }
    }

    cudaFuncSetAttribute(attn_kernel, cudaFuncAttributeMaxDynamicSharedMemorySize, ATTN_SMEM);

    qkv_kernel<<<dim3(64, 24), 256>>>(seqp, W[0], B[0], W[1], B[1], W[2], B[2], posp);
    attn_kernel<<<dim3(32, 16), 256, ATTN_SMEM>>>(maskp);
    oproj_kernel<<<dim3(64, 8), 256>>>(W[3], B[3], (float*)d_out);
}

// round 11
// speedup vs baseline: 1.5657x; 1.0052x over previous
#include <cuda_runtime.h>

#define NB   2
#define SEQ  2048
#define DM   512
#define NH   8
#define HD   64
#define GHD  (NB*NH)      /* 16 global heads */
#define EPSV 1e-8f

typedef unsigned long long u64;

// ---------------- packed f32x2 helpers (FFMA2 only reachable via PTX) ----------------
__device__ __forceinline__ u64 pack2(float lo, float hi) {
    u64 r;
    asm("mov.b64 %0, {%1, %2};" : "=l"(r)
        : "r"(__float_as_uint(lo)), "r"(__float_as_uint(hi)));
    return r;
}
__device__ __forceinline__ void unpack2(u64 v, float& lo, float& hi) {
    unsigned a, b;
    asm("mov.b64 {%0, %1}, %2;" : "=r"(a), "=r"(b) : "l"(v));
    lo = __uint_as_float(a); hi = __uint_as_float(b);
}
__device__ __forceinline__ void fma2(u64& d, u64 a, u64 b) {
    asm("fma.rn.f32x2 %0, %1, %2, %3;" : "=l"(d) : "l"(a), "l"(b), "l"(d));
}

// ---------------- scratch (static device globals: no allocation) ----------------
__device__ float g_Q[GHD*SEQ*HD];
__device__ float g_K[GHD*SEQ*HD];
__device__ float g_V[GHD*SEQ*HD];
__device__ float g_att[NB*SEQ*DM];

// ================= xPos rotary helper =================
__device__ __forceinline__ void rope_pair(float& x1, float& x2, int deven, float pf, bool down)
{
    float sv   = ((float)deven + 25.6f) * (1.0f / 89.6f);
    float invf = powf(10000.0f, -(float)deven * (1.0f / 64.0f));
    float th   = pf * invf;
    float sn, cs;
    sincosf(th, &sn, &cs);
    float sc = powf(sv, pf * (1.0f / 512.0f));
    if (down) sc = 1.0f / sc;
    float y1 = (x1 * cs - x2 * sn) * sc;
    float y2 = (x2 * cs + x1 * sn) * sc;
    x1 = y1; x2 = y2;
}

// ================= Kernel 1: fused QKV projection (R7: 64x64 tile, 4x4/thread) =================
__global__ __launch_bounds__(256) void qkv_kernel(
    const float* __restrict__ X,
    const float* __restrict__ Wq, const float* __restrict__ bq,
    const float* __restrict__ Wk, const float* __restrict__ bk,
    const float* __restrict__ Wv, const float* __restrict__ bv,
    const int*  __restrict__ positions)
{
    __shared__ float Xs[16][68];
    __shared__ float Ws[16][68];

    const int tid = threadIdx.x;
    const int tx  = tid & 15;
    const int ty  = tid >> 4;
    const int r0  = blockIdx.x * 64;
    const int c0  = blockIdx.y * 64;          // 0..1535
    const int kind = c0 / DM;                  // 0=Q 1=K 2=V
    const int cW   = c0 % DM;

    const float* W    = (kind == 0) ? Wq : (kind == 1) ? Wk : Wv;
    const float* bias = (kind == 0) ? bq : (kind == 1) ? bk : bv;

    u64 acc2[2][4];
    #pragma unroll
    for (int i = 0; i < 2; ++i)
        #pragma unroll
        for (int j = 0; j < 4; ++j) acc2[i][j] = 0ull;

    const int lr = tid >> 2;      // 0..63
    const int lk = tid & 3;       // float4 index within 16-wide K chunk

    for (int kb = 0; kb < DM; kb += 16) {
        float4 xa = *(const float4*)&X[(size_t)(r0 + lr) * DM + kb + lk * 4];
        float4 wa = *(const float4*)&W[(size_t)(cW + lr) * DM + kb + lk * 4];
        Xs[lk*4+0][lr] = xa.x; Xs[lk*4+1][lr] = xa.y; Xs[lk*4+2][lr] = xa.z; Xs[lk*4+3][lr] = xa.w;
        Ws[lk*4+0][lr] = wa.x; Ws[lk*4+1][lr] = wa.y; Ws[lk*4+2][lr] = wa.z; Ws[lk*4+3][lr] = wa.w;
        __syncthreads();

        #pragma unroll
        for (int k = 0; k < 16; ++k) {
            ulonglong2 ap = *(const ulonglong2*)&Xs[k][ty * 4];  // (a0,a1),(a2,a3)
            float4 b = *(const float4*)&Ws[k][tx * 4];
            u64 b0 = pack2(b.x, b.x), b1 = pack2(b.y, b.y);
            u64 b2 = pack2(b.z, b.z), b3 = pack2(b.w, b.w);
            fma2(acc2[0][0], ap.x, b0); fma2(acc2[0][1], ap.x, b1);
            fma2(acc2[0][2], ap.x, b2); fma2(acc2[0][3], ap.x, b3);
            fma2(acc2[1][0], ap.y, b0); fma2(acc2[1][1], ap.y, b1);
            fma2(acc2[1][2], ap.y, b2); fma2(acc2[1][3], ap.y, b3);
        }
        __syncthreads();
    }

    float acc[4][4];
    #pragma unroll
    for (int i2 = 0; i2 < 2; ++i2)
        #pragma unroll
        for (int j = 0; j < 4; ++j)
            unpack2(acc2[i2][j], acc[2*i2][j], acc[2*i2+1][j]);

    const int h = cW / HD;
    const int dbase = tx * 4;
    float* outbuf = (kind == 0) ? g_Q : (kind == 1) ? g_K : g_V;

    #pragma unroll
    for (int i = 0; i < 4; ++i) {
        int r = r0 + ty * 4 + i;
        int n = r >> 11, s = r & 2047;
        float v0 = acc[i][0] + bias[cW + dbase + 0];
        float v1 = acc[i][1] + bias[cW + dbase + 1];
        float v2 = acc[i][2] + bias[cW + dbase + 2];
        float v3 = acc[i][3] + bias[cW + dbase + 3];
        if (kind != 2) {
            if (kind == 0) { v0 *= 0.125f; v1 *= 0.125f; v2 *= 0.125f; v3 *= 0.125f; }
            float pf = (float)positions[r];
            bool down = (kind == 1);
            rope_pair(v0, v1, dbase + 0, pf, down);
            rope_pair(v2, v3, dbase + 2, pf, down);
        }
        float* dst = outbuf + ((size_t)(n * NH + h) * SEQ + s) * HD + dbase;
        *(float4*)dst = make_float4(v0, v1, v2, v3);
    }
}

// ================= Kernel 2: fused attention (R7 base + ASd weights + reg boundary, NO prefetch) =================
// smem: QS/KS/VS/ASt [64][68] floats + ASd [64][66] float2 + WB/MS
#define ATTN_SMEM ((4*64*68 + 2*64*66 + 2*64) * 4)

__global__ __launch_bounds__(256, 2) void attn_kernel(const float* __restrict__ mask)
{
    extern __shared__ float sm[];
    float*  QS  = sm;                        // [64][68]
    float*  KS  = QS + 64 * 68;              // [64][68]
    float*  VS  = KS + 64 * 68;              // [64][68]
    float*  ASt = VS + 64 * 68;              // transposed sigmoid A [col][row], stride 68
    float2* ASd = (float2*)(ASt + 64 * 68);  // duplicated weights [col t][row r], stride 66
    float*  WB  = (float*)(ASd + 64 * 66);   // boundary weights (64)
    float*  MS  = WB + 64;                   // input_mask tile (64)

    const int tid = threadIdx.x;
    const int tx  = tid & 15;
    const int ty  = tid >> 4;
    const int gh  = blockIdx.y;
    const int n   = gh >> 3;
    const int rb  = (int)(gridDim.x - 1 - blockIdx.x);   // heavy blocks launch first
    const int s0  = rb * 64;

    const float* Qg = g_Q + (size_t)gh * SEQ * HD;
    const float* Kg = g_K + (size_t)gh * SEQ * HD;
    const float* Vg = g_V + (size_t)gh * SEQ * HD;

    // load Q tile
    for (int it = tid; it < 64 * 16; it += 256) {
        int rr = it >> 4, f4 = it & 15;
        *(float4*)&QS[rr * 68 + f4 * 4] = *(const float4*)&Qg[(size_t)(s0 + rr) * HD + f4 * 4];
    }

    // per-row scan carries (threads 0..63 own row tid)
    float cA = 0.0f;
    float cP = 1.0f;
    float4 vb_prev = make_float4(0.f, 0.f, 0.f, 0.f);   // V row 0 of previously processed tile

    // out2[i][j2]: row ty*4+i, col pair (tx*4+2*j2, +1)
    u64 out2[4][2];
    #pragma unroll
    for (int i = 0; i < 4; ++i) { out2[i][0] = 0ull; out2[i][1] = 0ull; }

    __syncthreads();

    for (int jb = rb; jb >= 0; --jb) {
        const int lo = jb * 64;

        // direct smem loads (L2-resident: ~250 cyc exposed once per ~4000-cyc tile)
        for (int it = tid; it < 64 * 16; it += 256) {
            int rr = it >> 4, f4 = it & 15;
            *(float4*)&KS[rr * 68 + f4 * 4] = *(const float4*)&Kg[(size_t)(lo + rr) * HD + f4 * 4];
            *(float4*)&VS[rr * 68 + f4 * 4] = *(const float4*)&Vg[(size_t)(lo + rr) * HD + f4 * 4];
        }
        if (tid < 64) MS[tid] = mask[n * SEQ + lo + tid];
        __syncthreads();                               // (a)

        // ---- S = Q K^T (64x64x64), packed along d ----
        u64 acc2[4][4];
        #pragma unroll
        for (int i = 0; i < 4; ++i)
            #pragma unroll
            for (int j = 0; j < 4; ++j) acc2[i][j] = 0ull;

        #pragma unroll 4
        for (int d = 0; d < 64; d += 4) {
            ulonglong2 qa[4], kb[4];
            #pragma unroll
            for (int i = 0; i < 4; ++i) qa[i] = *(const ulonglong2*)&QS[(ty * 4 + i) * 68 + d];
            #pragma unroll
            for (int j = 0; j < 4; ++j) kb[j] = *(const ulonglong2*)&KS[(tx * 4 + j) * 68 + d];
            #pragma unroll
            for (int i = 0; i < 4; ++i)
                #pragma unroll
                for (int j = 0; j < 4; ++j) {
                    fma2(acc2[i][j], qa[i].x, kb[j].x);
                    fma2(acc2[i][j], qa[i].y, kb[j].y);
                }
        }
        float sa[4][4];
        #pragma unroll
        for (int i = 0; i < 4; ++i)
            #pragma unroll
            for (int j = 0; j < 4; ++j) {
                float l, h; unpack2(acc2[i][j], l, h);
                sa[i][j] = l + h;
            }

        // ---- A = sigmoid(S) * mask * causal, stored TRANSPOSED: ASt[c][r] ----
        #pragma unroll
        for (int j = 0; j < 4; ++j) {
            int tg = lo + tx * 4 + j;
            float mj = MS[tx * 4 + j];
            float w4[4];
            #pragma unroll
            for (int i = 0; i < 4; ++i) {
                int sg = s0 + ty * 4 + i;
                float a = 0.0f;
                if (tg <= sg)
                    a = __fdividef(mj, 1.0f + __expf(-sa[i][j]));
                w4[i] = a;
            }
            *(float4*)&ASt[(tx * 4 + j) * 68 + ty * 4] = make_float4(w4[0], w4[1], w4[2], w4[3]);
        }
        __syncthreads();                               // (b)

        // ---- per-row serial suffix-product scan (R7-proven), writes duplicated weights ----
        if (tid < 64) {
            const int r = tid;
            float lA = cA, lP = cP;
            for (int c = 63; c >= 0; --c) {
                float a  = ASt[c * 68 + r];
                float Pn = ((1.0f - a) + EPSV) * lP;
                float w  = lA * Pn;
                if (c == 63) WB[r] = w;
                else         ASd[(c + 1) * 66 + r] = make_float2(w, w);
                lA = a; lP = Pn;
            }
            float w0 = (jb == 0) ? lA : 0.0f;
            ASd[r] = make_float2(w0, w0);
            cA = lA; cP = lP;
        }
        __syncthreads();                               // (c)

        // ---- out += W_tile * V_tile (duplicated weights: no pack movs) ----
        #pragma unroll 8
        for (int c = 0; c < 64; ++c) {
            const float2* wrow = &ASd[c * 66 + ty * 4];
            ulonglong2 wA = *(const ulonglong2*)wrow;        // (w0,w0),(w1,w1)
            ulonglong2 wC = *(const ulonglong2*)(wrow + 2);  // (w2,w2),(w3,w3)
            ulonglong2 vv = *(const ulonglong2*)&VS[c * 68 + tx * 4];  // (v0,v1),(v2,v3)
            fma2(out2[0][0], wA.x, vv.x); fma2(out2[0][1], wA.x, vv.y);
            fma2(out2[1][0], wA.y, vv.x); fma2(out2[1][1], wA.y, vv.y);
            fma2(out2[2][0], wC.x, vv.x); fma2(out2[2][1], wC.x, vv.y);
            fma2(out2[3][0], wC.y, vv.x); fma2(out2[3][1], wC.y, vv.y);
        }
        // boundary column: weight WB (this scan) x V row 0 of PREVIOUS tile (registers)
        {
            u64 vbx = pack2(vb_prev.x, vb_prev.y);
            u64 vby = pack2(vb_prev.z, vb_prev.w);
            #pragma unroll
            for (int i = 0; i < 4; ++i) {
                float wv = WB[ty * 4 + i];
                u64 wd = pack2(wv, wv);
                fma2(out2[i][0], wd, vbx);
                fma2(out2[i][1], wd, vby);
            }
        }
        // capture V row 0 of THIS tile before smem is recycled
        vb_prev = *(const float4*)&VS[0 * 68 + tx * 4];
        __syncthreads();                               // (d)
    }

    // write attended in (N, S, H*64) layout for the output projection
    const int h = gh & 7;
    #pragma unroll
    for (int i = 0; i < 4; ++i) {
        float o0, o1, o2, o3;
        unpack2(out2[i][0], o0, o1);
        unpack2(out2[i][1], o2, o3);
        int s = s0 + ty * 4 + i;
        float* dst = g_att + ((size_t)(n * SEQ + s)) * DM + h * HD + tx * 4;
        *(float4*)dst = make_float4(o0, o1, o2, o3);
    }
}

// ================= Kernel 3: output projection (R7) =================
__global__ __launch_bounds__(256) void oproj_kernel(
    const float* __restrict__ Wo, const float* __restrict__ bo,
    float* __restrict__ outp)
{
    __shared__ float Xs[16][68];
    __shared__ float Ws[16][68];

    const int tid = threadIdx.x;
    const int tx  = tid & 15;
    const int ty  = tid >> 4;
    const int r0  = blockIdx.x * 64;
    const int c0  = blockIdx.y * 64;

    u64 acc2[2][4];
    #pragma unroll
    for (int i = 0; i < 2; ++i)
        #pragma unroll
        for (int j = 0; j < 4; ++j) acc2[i][j] = 0ull;

    const int lr = tid >> 2;
    const int lk = tid & 3;

    for (int kb = 0; kb < DM; kb += 16) {
        float4 xa = *(const float4*)&g_att[(size_t)(r0 + lr) * DM + kb + lk * 4];
        float4 wa = *(const float4*)&Wo[(size_t)(c0 + lr) * DM + kb + lk * 4];
        Xs[lk*4+0][lr] = xa.x; Xs[lk*4+1][lr] = xa.y; Xs[lk*4+2][lr] = xa.z; Xs[lk*4+3][lr] = xa.w;
        Ws[lk*4+0][lr] = wa.x; Ws[lk*4+1][lr] = wa.y; Ws[lk*4+2][lr] = wa.z; Ws[lk*4+3][lr] = wa.w;
        __syncthreads();

        #pragma unroll
        for (int k = 0; k < 16; ++k) {
            ulonglong2 ap = *(const ulonglong2*)&Xs[k][ty * 4];
            float4 b = *(const float4*)&Ws[k][tx * 4];
            u64 b0 = pack2(b.x, b.x), b1 = pack2(b.y, b.y);
            u64 b2 = pack2(b.z, b.z), b3 = pack2(b.w, b.w);
            fma2(acc2[0][0], ap.x, b0); fma2(acc2[0][1], ap.x, b1);
            fma2(acc2[0][2], ap.x, b2); fma2(acc2[0][3], ap.x, b3);
            fma2(acc2[1][0], ap.y, b0); fma2(acc2[1][1], ap.y, b1);
            fma2(acc2[1][2], ap.y, b2); fma2(acc2[1][3], ap.y, b3);
        }
        __syncthreads();
    }

    float acc[4][4];
    #pragma unroll
    for (int i2 = 0; i2 < 2; ++i2)
        #pragma unroll
        for (int j = 0; j < 4; ++j)
            unpack2(acc2[i2][j], acc[2*i2][j], acc[2*i2+1][j]);

    #pragma unroll
    for (int i = 0; i < 4; ++i) {
        int r = r0 + ty * 4 + i;
        float b0 = bo[c0 + tx * 4 + 0];
        float b1 = bo[c0 + tx * 4 + 1];
        float b2 = bo[c0 + tx * 4 + 2];
        float b3 = bo[c0 + tx * 4 + 3];
        *(float4*)&outp[(size_t)r * DM + c0 + tx * 4] =
            make_float4(acc[i][0] + b0, acc[i][1] + b1, acc[i][2] + b2, acc[i][3] + b3);
    }
}

// ================= host launcher =================
extern "C" void kernel_launch(void* const* d_in, const int* in_sizes, int n_in,
                              void* d_out, int out_size)
{
    const float* seqp = nullptr;
    const float* maskp = nullptr;
    const int*   posp = nullptr;
    const float* W[4] = {nullptr, nullptr, nullptr, nullptr};
    const float* B[4] = {nullptr, nullptr, nullptr, nullptr};
    int nw = 0, nb = 0, n4096 = 0;
    for (int i = 0; i < n_in; ++i) {
        int sz = in_sizes[i];
        if (sz == NB * SEQ * DM) {
            seqp = (const float*)d_in[i];
        } else if (sz == DM * DM) {
            if (nw < 4) W[nw++] = (const float*)d_in[i];
        } else if (sz == DM) {
            if (nb < 4) B[nb++] = (const float*)d_in[i];
        } else if (sz == NB * SEQ) {
            if (n4096 == 0) maskp = (const float*)d_in[i];
            else            posp  = (const int*)d_in[i];
            ++n4096;
        }
    }

    cudaFuncSetAttribute(attn_kernel, cudaFuncAttributeMaxDynamicSharedMemorySize, ATTN_SMEM);

    qkv_kernel<<<dim3(64, 24), 256>>>(seqp, W[0], B[0], W[1], B[1], W[2], B[2], posp);
    attn_kernel<<<dim3(32, 16), 256, ATTN_SMEM>>>(maskp);
    oproj_kernel<<<dim3(64, 8), 256>>>(W[3], B[3], (float*)d_out);
}

// round 13
// speedup vs baseline: 2.3705x; 1.5140x over previous
#include <cuda_runtime.h>
#include <cuda_bf16.h>

#define NB   2
#define SEQ  2048
#define DM   512
#define NH   8
#define HD   64
#define GHD  (NB*NH)      /* 16 global heads */
#define EPSV 1e-8f

typedef unsigned long long u64;

// ---------------- packed f32x2 helpers (for the fp32 projection kernels) ----------------
__device__ __forceinline__ u64 pack2(float lo, float hi) {
    u64 r;
    asm("mov.b64 %0, {%1, %2};" : "=l"(r)
        : "r"(__float_as_uint(lo)), "r"(__float_as_uint(hi)));
    return r;
}
__device__ __forceinline__ void unpack2(u64 v, float& lo, float& hi) {
    unsigned a, b;
    asm("mov.b64 {%0, %1}, %2;" : "=r"(a), "=r"(b) : "l"(v));
    lo = __uint_as_float(a); hi = __uint_as_float(b);
}
__device__ __forceinline__ void fma2(u64& d, u64 a, u64 b) {
    asm("fma.rn.f32x2 %0, %1, %2, %3;" : "=l"(d) : "l"(a), "l"(b), "l"(d));
}

// ---------------- tensor-core helpers (textbook sm80 pattern, valid on sm_103a) ----------------
__device__ __forceinline__ void ldsm4(unsigned& r0, unsigned& r1, unsigned& r2, unsigned& r3, unsigned addr) {
    asm volatile("ldmatrix.sync.aligned.m8n8.x4.shared.b16 {%0,%1,%2,%3}, [%4];"
        : "=r"(r0), "=r"(r1), "=r"(r2), "=r"(r3) : "r"(addr));
}
__device__ __forceinline__ void ldsm2(unsigned& r0, unsigned& r1, unsigned addr) {
    asm volatile("ldmatrix.sync.aligned.m8n8.x2.shared.b16 {%0,%1}, [%2];"
        : "=r"(r0), "=r"(r1) : "r"(addr));
}
__device__ __forceinline__ void mma16816(float* c, unsigned a0, unsigned a1, unsigned a2, unsigned a3,
                                         unsigned b0, unsigned b1) {
    asm volatile("mma.sync.aligned.m16n8k16.row.col.f32.bf16.bf16.f32 "
        "{%0,%1,%2,%3}, {%4,%5,%6,%7}, {%8,%9}, {%0,%1,%2,%3};"
        : "+f"(c[0]), "+f"(c[1]), "+f"(c[2]), "+f"(c[3])
        : "r"(a0), "r"(a1), "r"(a2), "r"(a3), "r"(b0), "r"(b1));
}
__device__ __forceinline__ void bf16split(float x, __nv_bfloat16& h, __nv_bfloat16& l) {
    h = __float2bfloat16(x);
    l = __float2bfloat16(x - __bfloat162float(h));
}

// ---------------- scratch (static device globals: no allocation) ----------------
__device__ float g_Q[GHD*SEQ*HD];
__device__ float g_K[GHD*SEQ*HD];
__device__ float g_V[GHD*SEQ*HD];
__device__ float g_att[NB*SEQ*DM];

// ================= xPos rotary helper =================
__device__ __forceinline__ void rope_pair(float& x1, float& x2, int deven, float pf, bool down)
{
    float sv   = ((float)deven + 25.6f) * (1.0f / 89.6f);
    float invf = powf(10000.0f, -(float)deven * (1.0f / 64.0f));
    float th   = pf * invf;
    float sn, cs;
    sincosf(th, &sn, &cs);
    float sc = powf(sv, pf * (1.0f / 512.0f));
    if (down) sc = 1.0f / sc;
    float y1 = (x1 * cs - x2 * sn) * sc;
    float y2 = (x2 * cs + x1 * sn) * sc;
    x1 = y1; x2 = y2;
}

// ================= Kernel 1: fused QKV projection (R7-proven) =================
__global__ __launch_bounds__(256) void qkv_kernel(
    const float* __restrict__ X,
    const float* __restrict__ Wq, const float* __restrict__ bq,
    const float* __restrict__ Wk, const float* __restrict__ bk,
    const float* __restrict__ Wv, const float* __restrict__ bv,
    const int*  __restrict__ positions)
{
    __shared__ float Xs[16][68];
    __shared__ float Ws[16][68];

    const int tid = threadIdx.x;
    const int tx  = tid & 15;
    const int ty  = tid >> 4;
    const int r0  = blockIdx.x * 64;
    const int c0  = blockIdx.y * 64;
    const int kind = c0 / DM;
    const int cW   = c0 % DM;

    const float* W    = (kind == 0) ? Wq : (kind == 1) ? Wk : Wv;
    const float* bias = (kind == 0) ? bq : (kind == 1) ? bk : bv;

    u64 acc2[2][4];
    #pragma unroll
    for (int i = 0; i < 2; ++i)
        #pragma unroll
        for (int j = 0; j < 4; ++j) acc2[i][j] = 0ull;

    const int lr = tid >> 2;
    const int lk = tid & 3;

    for (int kb = 0; kb < DM; kb += 16) {
        float4 xa = *(const float4*)&X[(size_t)(r0 + lr) * DM + kb + lk * 4];
        float4 wa = *(const float4*)&W[(size_t)(cW + lr) * DM + kb + lk * 4];
        Xs[lk*4+0][lr] = xa.x; Xs[lk*4+1][lr] = xa.y; Xs[lk*4+2][lr] = xa.z; Xs[lk*4+3][lr] = xa.w;
        Ws[lk*4+0][lr] = wa.x; Ws[lk*4+1][lr] = wa.y; Ws[lk*4+2][lr] = wa.z; Ws[lk*4+3][lr] = wa.w;
        __syncthreads();

        #pragma unroll
        for (int k = 0; k < 16; ++k) {
            ulonglong2 ap = *(const ulonglong2*)&Xs[k][ty * 4];
            float4 b = *(const float4*)&Ws[k][tx * 4];
            u64 b0 = pack2(b.x, b.x), b1 = pack2(b.y, b.y);
            u64 b2 = pack2(b.z, b.z), b3 = pack2(b.w, b.w);
            fma2(acc2[0][0], ap.x, b0); fma2(acc2[0][1], ap.x, b1);
            fma2(acc2[0][2], ap.x, b2); fma2(acc2[0][3], ap.x, b3);
            fma2(acc2[1][0], ap.y, b0); fma2(acc2[1][1], ap.y, b1);
            fma2(acc2[1][2], ap.y, b2); fma2(acc2[1][3], ap.y, b3);
        }
        __syncthreads();
    }

    float acc[4][4];
    #pragma unroll
    for (int i2 = 0; i2 < 2; ++i2)
        #pragma unroll
        for (int j = 0; j < 4; ++j)
            unpack2(acc2[i2][j], acc[2*i2][j], acc[2*i2+1][j]);

    const int h = cW / HD;
    const int dbase = tx * 4;
    float* outbuf = (kind == 0) ? g_Q : (kind == 1) ? g_K : g_V;

    #pragma unroll
    for (int i = 0; i < 4; ++i) {
        int r = r0 + ty * 4 + i;
        int n = r >> 11, s = r & 2047;
        float v0 = acc[i][0] + bias[cW + dbase + 0];
        float v1 = acc[i][1] + bias[cW + dbase + 1];
        float v2 = acc[i][2] + bias[cW + dbase + 2];
        float v3 = acc[i][3] + bias[cW + dbase + 3];
        if (kind != 2) {
            if (kind == 0) { v0 *= 0.125f; v1 *= 0.125f; v2 *= 0.125f; v3 *= 0.125f; }
            float pf = (float)positions[r];
            bool down = (kind == 1);
            rope_pair(v0, v1, dbase + 0, pf, down);
            rope_pair(v2, v3, dbase + 2, pf, down);
        }
        float* dst = outbuf + ((size_t)(n * NH + h) * SEQ + s) * HD + dbase;
        *(float4*)dst = make_float4(v0, v1, v2, v3);
    }
}

// ================= Kernel 2: tensor-core attention (bf16 hi/lo split MMA + fp32 scan) =================
// smem layout (bytes), bf16 tiles use stride 72 elements (144 B rows, 16B-aligned):
#define SO_QH   0
#define SO_QL   9216
#define SO_KH   18432
#define SO_KL   27648
#define SO_VTH  36864
#define SO_VTL  46080
#define SO_WH   55296
#define SO_WL   64512
#define SO_AST  73728            /* fp32 [col][row], stride 68 */
#define SO_WB   91136            /* fp32 [64] boundary weights */
#define SO_MS   91392            /* fp32 [64] mask tile */
#define ATTN_SMEM 91648

__global__ __launch_bounds__(256, 2) void attn_kernel(const float* __restrict__ mask)
{
    extern __shared__ char smc[];
    __nv_bfloat16* QH  = (__nv_bfloat16*)(smc + SO_QH);
    __nv_bfloat16* QL  = (__nv_bfloat16*)(smc + SO_QL);
    __nv_bfloat16* KH  = (__nv_bfloat16*)(smc + SO_KH);
    __nv_bfloat16* KL  = (__nv_bfloat16*)(smc + SO_KL);
    __nv_bfloat16* VTH = (__nv_bfloat16*)(smc + SO_VTH);
    __nv_bfloat16* VTL = (__nv_bfloat16*)(smc + SO_VTL);
    __nv_bfloat16* WH  = (__nv_bfloat16*)(smc + SO_WH);
    __nv_bfloat16* WL  = (__nv_bfloat16*)(smc + SO_WL);
    float* ASt = (float*)(smc + SO_AST);
    float* WB  = (float*)(smc + SO_WB);
    float* MS  = (float*)(smc + SO_MS);

    const unsigned sb = (unsigned)__cvta_generic_to_shared(smc);

    const int tid  = threadIdx.x;
    const int warp = tid >> 5;
    const int lane = tid & 31;
    const int wr   = (warp >> 1) * 16;     // warp row offset (0/16/32/48)
    const int wc   = (warp & 1) * 32;      // warp col offset (0/32)
    const int gh   = blockIdx.y;
    const int nb   = gh >> 3;
    const int hh   = gh & 7;
    const int rb   = (int)(gridDim.x - 1 - blockIdx.x);   // heavy blocks first
    const int s0   = rb * 64;

    const float* Qg = g_Q + (size_t)gh * SEQ * HD;
    const float* Kg = g_K + (size_t)gh * SEQ * HD;
    const float* Vg = g_V + (size_t)gh * SEQ * HD;

    // ---- convert Q tile to bf16 hi/lo (once) ----
    for (int it = tid; it < 64 * 16; it += 256) {
        int rr = it >> 4, f4 = it & 15;
        float4 q = *(const float4*)&Qg[(size_t)(s0 + rr) * HD + f4 * 4];
        __nv_bfloat16 h0,h1,h2,h3,l0,l1,l2,l3;
        bf16split(q.x,h0,l0); bf16split(q.y,h1,l1); bf16split(q.z,h2,l2); bf16split(q.w,h3,l3);
        int idx = rr * 72 + f4 * 4;
        *(__nv_bfloat162*)&QH[idx]   = __halves2bfloat162(h0,h1);
        *(__nv_bfloat162*)&QH[idx+2] = __halves2bfloat162(h2,h3);
        *(__nv_bfloat162*)&QL[idx]   = __halves2bfloat162(l0,l1);
        *(__nv_bfloat162*)&QL[idx+2] = __halves2bfloat162(l2,l3);
    }

    // scan carries
    float cA = 0.0f;
    float cP = 1.0f;

    // persistent AV accumulators: o[n][r], n = n8-tile, r = frag reg
    float o[4][4];
    #pragma unroll
    for (int n = 0; n < 4; ++n)
        #pragma unroll
        for (int r = 0; r < 4; ++r) o[n][r] = 0.0f;

    // ldmatrix per-lane address components (element offsets, ×2 bytes later)
    const unsigned aoffA = (unsigned)((lane & 15) * 72 + (lane >> 4) * 8);        // A-frag (x4)
    const unsigned boffB = (unsigned)((lane & 7) * 72 + ((lane >> 3) & 1) * 8);   // B-frag (x2)

    for (int jb = rb; jb >= 0; --jb) {
        const int lo = jb * 64;

        // ---- load+convert K (row-major) and V (transposed) ----
        for (int it = tid; it < 64 * 16; it += 256) {
            int rr = it >> 4, f4 = it & 15;
            float4 k = *(const float4*)&Kg[(size_t)(lo + rr) * HD + f4 * 4];
            __nv_bfloat16 h0,h1,h2,h3,l0,l1,l2,l3;
            bf16split(k.x,h0,l0); bf16split(k.y,h1,l1); bf16split(k.z,h2,l2); bf16split(k.w,h3,l3);
            int idx = rr * 72 + f4 * 4;
            *(__nv_bfloat162*)&KH[idx]   = __halves2bfloat162(h0,h1);
            *(__nv_bfloat162*)&KH[idx+2] = __halves2bfloat162(h2,h3);
            *(__nv_bfloat162*)&KL[idx]   = __halves2bfloat162(l0,l1);
            *(__nv_bfloat162*)&KL[idx+2] = __halves2bfloat162(l2,l3);
        }
        {
            int t  = tid & 63;
            int dq = (tid >> 6) * 16;
            #pragma unroll
            for (int i = 0; i < 4; ++i) {
                float4 v = *(const float4*)&Vg[(size_t)(lo + t) * HD + dq + i * 4];
                __nv_bfloat16 h, l;
                int d = dq + i * 4;
                bf16split(v.x,h,l); VTH[(d+0)*72 + t] = h; VTL[(d+0)*72 + t] = l;
                bf16split(v.y,h,l); VTH[(d+1)*72 + t] = h; VTL[(d+1)*72 + t] = l;
                bf16split(v.z,h,l); VTH[(d+2)*72 + t] = h; VTL[(d+2)*72 + t] = l;
                bf16split(v.w,h,l); VTH[(d+3)*72 + t] = h; VTL[(d+3)*72 + t] = l;
            }
        }
        if (tid < 64) MS[tid] = mask[nb * SEQ + lo + tid];
        __syncthreads();                               // (a)

        // ---- S = Q K^T via 3-pass bf16 split MMA ----
        float sc[4][4];
        #pragma unroll
        for (int n = 0; n < 4; ++n)
            #pragma unroll
            for (int r = 0; r < 4; ++r) sc[n][r] = 0.0f;

        #pragma unroll
        for (int kt = 0; kt < 4; ++kt) {
            unsigned aH0,aH1,aH2,aH3, aL0,aL1,aL2,aL3;
            unsigned abase = (aoffA + (unsigned)(kt * 16)) * 2u;
            ldsm4(aH0,aH1,aH2,aH3, sb + SO_QH + (unsigned)(wr * 144) + abase);
            ldsm4(aL0,aL1,aL2,aL3, sb + SO_QL + (unsigned)(wr * 144) + abase);
            #pragma unroll
            for (int n = 0; n < 4; ++n) {
                unsigned bH0,bH1,bL0,bL1;
                unsigned bbase = (boffB + (unsigned)(kt * 16)) * 2u + (unsigned)((wc + n * 8) * 144);
                ldsm2(bH0,bH1, sb + SO_KH + bbase);
                ldsm2(bL0,bL1, sb + SO_KL + bbase);
                mma16816(sc[n], aH0,aH1,aH2,aH3, bH0,bH1);
                mma16816(sc[n], aL0,aL1,aL2,aL3, bH0,bH1);
                mma16816(sc[n], aH0,aH1,aH2,aH3, bL0,bL1);
            }
        }

        // ---- sigmoid * mask * causal on fragments -> ASt[col][row] ----
        {
            const int lrow = wr + (lane >> 2);       // local row (and +8)
            #pragma unroll
            for (int n = 0; n < 4; ++n) {
                const int lcol = wc + n * 8 + (lane & 3) * 2;  // local col (and +1)
                float m0 = MS[lcol], m1 = MS[lcol + 1];
                #pragma unroll
                for (int r = 0; r < 4; ++r) {
                    int lr_ = lrow + (r >> 1) * 8;
                    int lc_ = lcol + (r & 1);
                    float mj = (r & 1) ? m1 : m0;
                    float a = 0.0f;
                    if (lo + lc_ <= s0 + lr_)
                        a = __fdividef(mj, 1.0f + __expf(-sc[n][r]));
                    ASt[lc_ * 68 + lr_] = a;
                }
            }
        }
        __syncthreads();                               // (b)

        // ---- per-row serial suffix-product scan (R7-identical math), emit bf16 hi/lo weights ----
        if (tid < 64) {
            const int r = tid;
            float lA = cA, lP = cP;
            for (int c = 63; c >= 0; --c) {
                float a  = ASt[c * 68 + r];
                float Pn = ((1.0f - a) + EPSV) * lP;
                float w  = lA * Pn;
                if (c == 63) WB[r] = w;
                else {
                    __nv_bfloat16 h, l; bf16split(w, h, l);
                    WH[r * 72 + c + 1] = h; WL[r * 72 + c + 1] = l;
                }
                lA = a; lP = Pn;
            }
            float w0 = (jb == 0) ? lA : 0.0f;
            __nv_bfloat16 h, l; bf16split(w0, h, l);
            WH[r * 72] = h; WL[r * 72] = l;
            cA = lA; cP = lP;
        }
        __syncthreads();                               // (c)

        // ---- out += W * V via 3-pass bf16 split MMA (B = V^T in smem) ----
        #pragma unroll
        for (int kt = 0; kt < 4; ++kt) {
            unsigned aH0,aH1,aH2,aH3, aL0,aL1,aL2,aL3;
            unsigned abase = (aoffA + (unsigned)(kt * 16)) * 2u;
            ldsm4(aH0,aH1,aH2,aH3, sb + SO_WH + (unsigned)(wr * 144) + abase);
            ldsm4(aL0,aL1,aL2,aL3, sb + SO_WL + (unsigned)(wr * 144) + abase);
            #pragma unroll
            for (int n = 0; n < 4; ++n) {
                unsigned bH0,bH1,bL0,bL1;
                unsigned bbase = (boffB + (unsigned)(kt * 16)) * 2u + (unsigned)((wc + n * 8) * 144);
                ldsm2(bH0,bH1, sb + SO_VTH + bbase);
                ldsm2(bL0,bL1, sb + SO_VTL + bbase);
                mma16816(o[n], aH0,aH1,aH2,aH3, bH0,bH1);
                mma16816(o[n], aL0,aL1,aL2,aL3, bH0,bH1);
                mma16816(o[n], aH0,aH1,aH2,aH3, bL0,bL1);
            }
        }
        // boundary column: WB (this scan) x global V row lo+64 (= previous tile's row 0)
        if (jb < rb) {
            const float* vrow = &Vg[(size_t)(lo + 64) * HD];
            float wb0 = WB[wr + (lane >> 2)];
            float wb1 = WB[wr + (lane >> 2) + 8];
            #pragma unroll
            for (int n = 0; n < 4; ++n) {
                int d0 = wc + n * 8 + (lane & 3) * 2;
                float v0 = vrow[d0], v1 = vrow[d0 + 1];
                o[n][0] = fmaf(wb0, v0, o[n][0]);
                o[n][1] = fmaf(wb0, v1, o[n][1]);
                o[n][2] = fmaf(wb1, v0, o[n][2]);
                o[n][3] = fmaf(wb1, v1, o[n][3]);
            }
        }
        __syncthreads();                               // (d) protect smem for next tile
    }

    // ---- write attended fragments to g_att in (N, S, H*64) layout ----
    {
        const int lrow = wr + (lane >> 2);
        #pragma unroll
        for (int n = 0; n < 4; ++n) {
            const int d0 = wc + n * 8 + (lane & 3) * 2;
            #pragma unroll
            for (int r = 0; r < 4; ++r) {
                int s = s0 + lrow + (r >> 1) * 8;
                int d = d0 + (r & 1);
                g_att[((size_t)(nb * SEQ + s)) * DM + hh * HD + d] = o[n][r];
            }
        }
    }
}

// ================= Kernel 3: output projection (R7-proven) =================
__global__ __launch_bounds__(256) void oproj_kernel(
    const float* __restrict__ Wo, const float* __restrict__ bo,
    float* __restrict__ outp)
{
    __shared__ float Xs[16][68];
    __shared__ float Ws[16][68];

    const int tid = threadIdx.x;
    const int tx  = tid & 15;
    const int ty  = tid >> 4;
    const int r0  = blockIdx.x * 64;
    const int c0  = blockIdx.y * 64;

    u64 acc2[2][4];
    #pragma unroll
    for (int i = 0; i < 2; ++i)
        #pragma unroll
        for (int j = 0; j < 4; ++j) acc2[i][j] = 0ull;

    const int lr = tid >> 2;
    const int lk = tid & 3;

    for (int kb = 0; kb < DM; kb += 16) {
        float4 xa = *(const float4*)&g_att[(size_t)(r0 + lr) * DM + kb + lk * 4];
        float4 wa = *(const float4*)&Wo[(size_t)(c0 + lr) * DM + kb + lk * 4];
        Xs[lk*4+0][lr] = xa.x; Xs[lk*4+1][lr] = xa.y; Xs[lk*4+2][lr] = xa.z; Xs[lk*4+3][lr] = xa.w;
        Ws[lk*4+0][lr] = wa.x; Ws[lk*4+1][lr] = wa.y; Ws[lk*4+2][lr] = wa.z; Ws[lk*4+3][lr] = wa.w;
        __syncthreads();

        #pragma unroll
        for (int k = 0; k < 16; ++k) {
            ulonglong2 ap = *(const ulonglong2*)&Xs[k][ty * 4];
            float4 b = *(const float4*)&Ws[k][tx * 4];
            u64 b0 = pack2(b.x, b.x), b1 = pack2(b.y, b.y);
            u64 b2 = pack2(b.z, b.z), b3 = pack2(b.w, b.w);
            fma2(acc2[0][0], ap.x, b0); fma2(acc2[0][1], ap.x, b1);
            fma2(acc2[0][2], ap.x, b2); fma2(acc2[0][3], ap.x, b3);
            fma2(acc2[1][0], ap.y, b0); fma2(acc2[1][1], ap.y, b1);
            fma2(acc2[1][2], ap.y, b2); fma2(acc2[1][3], ap.y, b3);
        }
        __syncthreads();
    }

    float acc[4][4];
    #pragma unroll
    for (int i2 = 0; i2 < 2; ++i2)
        #pragma unroll
        for (int j = 0; j < 4; ++j)
            unpack2(acc2[i2][j], acc[2*i2][j], acc[2*i2+1][j]);

    #pragma unroll
    for (int i = 0; i < 4; ++i) {
        int r = r0 + ty * 4 + i;
        float b0 = bo[c0 + tx * 4 + 0];
        float b1 = bo[c0 + tx * 4 + 1];
        float b2 = bo[c0 + tx * 4 + 2];
        float b3 = bo[c0 + tx * 4 + 3];
        *(float4*)&outp[(size_t)r * DM + c0 + tx * 4] =
            make_float4(acc[i][0] + b0, acc[i][1] + b1, acc[i][2] + b2, acc[i][3] + b3);
    }
}

// ================= host launcher =================
extern "C" void kernel_launch(void* const* d_in, const int* in_sizes, int n_in,
                              void* d_out, int out_size)
{
    const float* seqp = nullptr;
    const float* maskp = nullptr;
    const int*   posp = nullptr;
    const float* W[4] = {nullptr, nullptr, nullptr, nullptr};
    const float* B[4] = {nullptr, nullptr, nullptr, nullptr};
    int nw = 0, nbb = 0, n4096 = 0;
    for (int i = 0; i < n_in; ++i) {
        int sz = in_sizes[i];
        if (sz == NB * SEQ * DM) {
            seqp = (const float*)d_in[i];
        } else if (sz == DM * DM) {
            if (nw < 4) W[nw++] = (const float*)d_in[i];
        } else if (sz == DM) {
            if (nbb < 4) B[nbb++] = (const float*)d_in[i];
        } else if (sz == NB * SEQ) {
            if (n4096 == 0) maskp = (const float*)d_in[i];
            else            posp  = (const int*)d_in[i];
            ++n4096;
        }
    }

    cudaFuncSetAttribute(attn_kernel, cudaFuncAttributeMaxDynamicSharedMemorySize, ATTN_SMEM);

    qkv_kernel<<<dim3(64, 24), 256>>>(seqp, W[0], B[0], W[1], B[1], W[2], B[2], posp);
    attn_kernel<<<dim3(32, 16), 256, ATTN_SMEM>>>(maskp);
    oproj_kernel<<<dim3(64, 8), 256>>>(W[3], B[3], (float*)d_out);
}

// round 14
// speedup vs baseline: 3.2105x; 1.3544x over previous
#include <cuda_runtime.h>
#include <cuda_bf16.h>

#define NB   2
#define SEQ  2048
#define DM   512
#define NH   8
#define HD   64
#define GHD  (NB*NH)      /* 16 global heads */
#define EPSV 1e-8f

// ---------------- tensor-core helpers (proven in R13) ----------------
__device__ __forceinline__ void ldsm4(unsigned& r0, unsigned& r1, unsigned& r2, unsigned& r3, unsigned addr) {
    asm volatile("ldmatrix.sync.aligned.m8n8.x4.shared.b16 {%0,%1,%2,%3}, [%4];"
        : "=r"(r0), "=r"(r1), "=r"(r2), "=r"(r3) : "r"(addr));
}
__device__ __forceinline__ void ldsm2(unsigned& r0, unsigned& r1, unsigned addr) {
    asm volatile("ldmatrix.sync.aligned.m8n8.x2.shared.b16 {%0,%1}, [%2];"
        : "=r"(r0), "=r"(r1) : "r"(addr));
}
__device__ __forceinline__ void mma16816(float* c, unsigned a0, unsigned a1, unsigned a2, unsigned a3,
                                         unsigned b0, unsigned b1) {
    asm volatile("mma.sync.aligned.m16n8k16.row.col.f32.bf16.bf16.f32 "
        "{%0,%1,%2,%3}, {%4,%5,%6,%7}, {%8,%9}, {%0,%1,%2,%3};"
        : "+f"(c[0]), "+f"(c[1]), "+f"(c[2]), "+f"(c[3])
        : "r"(a0), "r"(a1), "r"(a2), "r"(a3), "r"(b0), "r"(b1));
}
__device__ __forceinline__ void bf16split(float x, __nv_bfloat16& h, __nv_bfloat16& l) {
    h = __float2bfloat16(x);
    l = __float2bfloat16(x - __bfloat162float(h));
}

// ---------------- scratch (static device globals; all bf16 hi/lo pairs) ----------------
__device__ __nv_bfloat16 g_XH[NB*SEQ*DM], g_XL[NB*SEQ*DM];   // sequence
__device__ __nv_bfloat16 g_WH[4*DM*DM],  g_WL[4*DM*DM];      // Wq,Wk,Wv,Wo
__device__ __nv_bfloat16 g_QH[GHD*SEQ*HD], g_QL[GHD*SEQ*HD];
__device__ __nv_bfloat16 g_KH[GHD*SEQ*HD], g_KL[GHD*SEQ*HD];
__device__ __nv_bfloat16 g_VH[GHD*SEQ*HD], g_VL[GHD*SEQ*HD];
__device__ __nv_bfloat16 g_AH[NB*SEQ*DM],  g_AL[NB*SEQ*DM];  // attended

// ================= xPos rotary helper =================
__device__ __forceinline__ void rope_pair(float& x1, float& x2, int deven, float pf, bool down)
{
    float sv   = ((float)deven + 25.6f) * (1.0f / 89.6f);
    float invf = powf(10000.0f, -(float)deven * (1.0f / 64.0f));
    float th   = pf * invf;
    float sn, cs;
    sincosf(th, &sn, &cs);
    float sc = powf(sv, pf * (1.0f / 512.0f));
    if (down) sc = 1.0f / sc;
    float y1 = (x1 * cs - x2 * sn) * sc;
    float y2 = (x2 * cs + x1 * sn) * sc;
    x1 = y1; x2 = y2;
}

// ================= Kernel 0: one-shot fp32 -> bf16 hi/lo conversion =================
#define X_F4 ((NB*SEQ*DM)/4)     /* 524288 */
#define W_F4 ((DM*DM)/4)         /* 65536 = 2^16 */

__global__ __launch_bounds__(256) void convert_kernel(
    const float* __restrict__ X,
    const float* __restrict__ Wq, const float* __restrict__ Wk,
    const float* __restrict__ Wv, const float* __restrict__ Wo)
{
    int gid = blockIdx.x * 256 + threadIdx.x;          // float4 index
    const float* src; __nv_bfloat16 *dh, *dl; int off;
    if (gid < X_F4) {
        src = X; dh = g_XH; dl = g_XL; off = gid;
    } else {
        int t = gid - X_F4;
        int w = t >> 16;                // 65536 float4 per weight
        off   = t & (W_F4 - 1);
        src = (w == 0) ? Wq : (w == 1) ? Wk : (w == 2) ? Wv : Wo;
        dh = g_WH + w * DM * DM; dl = g_WL + w * DM * DM;
    }
    float4 v = ((const float4*)src)[off];
    __nv_bfloat16 h0,h1,h2,h3,l0,l1,l2,l3;
    bf16split(v.x,h0,l0); bf16split(v.y,h1,l1); bf16split(v.z,h2,l2); bf16split(v.w,h3,l3);
    __nv_bfloat162* ph = (__nv_bfloat162*)(dh + off * 4);
    __nv_bfloat162* pl = (__nv_bfloat162*)(dl + off * 4);
    ph[0] = __halves2bfloat162(h0,h1); ph[1] = __halves2bfloat162(h2,h3);
    pl[0] = __halves2bfloat162(l0,l1); pl[1] = __halves2bfloat162(l2,l3);
}

// ================= Kernel 1: QKV projection via 3-pass bf16-split MMA =================
// 64x64 output tile, k-loop over DM. Epilogue: bias + scale + rope, emit bf16 hi/lo QKV.
__global__ __launch_bounds__(256) void qkv_mma(
    const float* __restrict__ bq, const float* __restrict__ bk, const float* __restrict__ bv,
    const int* __restrict__ positions)
{
    __shared__ __nv_bfloat16 XHs[64*72], XLs[64*72], WHs[64*72], WLs[64*72];

    const int tid  = threadIdx.x;
    const int warp = tid >> 5;
    const int lane = tid & 31;
    const int wr   = (warp >> 1) * 16;
    const int wc   = (warp & 1) * 32;
    const int r0   = blockIdx.x * 64;          // seq rows (0..4095)
    const int c0   = blockIdx.y * 64;          // out cols (0..1535)
    const int kind = c0 / DM;                  // 0=Q 1=K 2=V
    const int cW   = c0 % DM;
    const int h    = cW >> 6;                  // head (tile width == head dim)

    const __nv_bfloat16* WHg = g_WH + (size_t)kind * DM * DM;
    const __nv_bfloat16* WLg = g_WL + (size_t)kind * DM * DM;

    const unsigned sXH = (unsigned)__cvta_generic_to_shared(XHs);
    const unsigned sXL = (unsigned)__cvta_generic_to_shared(XLs);
    const unsigned sWH = (unsigned)__cvta_generic_to_shared(WHs);
    const unsigned sWL = (unsigned)__cvta_generic_to_shared(WLs);

    float o[4][4];
    #pragma unroll
    for (int n = 0; n < 4; ++n)
        #pragma unroll
        for (int r = 0; r < 4; ++r) o[n][r] = 0.0f;

    const unsigned aoffA = (unsigned)((lane & 15) * 72 + (lane >> 4) * 8);
    const unsigned boffB = (unsigned)((lane & 7) * 72 + ((lane >> 3) & 1) * 8);

    for (int kb = 0; kb < DM; kb += 64) {
        for (int it = tid; it < 512; it += 256) {
            int rr = it >> 3, f8 = (it & 7) * 8;
            *(uint4*)&XHs[rr*72 + f8] = *(const uint4*)&g_XH[(size_t)(r0+rr)*DM + kb + f8];
            *(uint4*)&XLs[rr*72 + f8] = *(const uint4*)&g_XL[(size_t)(r0+rr)*DM + kb + f8];
            *(uint4*)&WHs[rr*72 + f8] = *(const uint4*)&WHg[(size_t)(cW+rr)*DM + kb + f8];
            *(uint4*)&WLs[rr*72 + f8] = *(const uint4*)&WLg[(size_t)(cW+rr)*DM + kb + f8];
        }
        __syncthreads();

        #pragma unroll
        for (int kt = 0; kt < 4; ++kt) {
            unsigned aH0,aH1,aH2,aH3, aL0,aL1,aL2,aL3;
            unsigned abase = (aoffA + (unsigned)(kt * 16)) * 2u + (unsigned)(wr * 144);
            ldsm4(aH0,aH1,aH2,aH3, sXH + abase);
            ldsm4(aL0,aL1,aL2,aL3, sXL + abase);
            #pragma unroll
            for (int n = 0; n < 4; ++n) {
                unsigned bH0,bH1,bL0,bL1;
                unsigned bbase = (boffB + (unsigned)(kt * 16)) * 2u + (unsigned)((wc + n * 8) * 144);
                ldsm2(bH0,bH1, sWH + bbase);
                ldsm2(bL0,bL1, sWL + bbase);
                mma16816(o[n], aH0,aH1,aH2,aH3, bH0,bH1);
                mma16816(o[n], aL0,aL1,aL2,aL3, bH0,bH1);
                mma16816(o[n], aH0,aH1,aH2,aH3, bL0,bL1);
            }
        }
        __syncthreads();
    }

    // ---- epilogue: bias (+Q scale) + rope on fragments, emit bf16 hi/lo ----
    const int lrow = wr + (lane >> 2);
    const int rA = r0 + lrow, rB = rA + 8;
    const int nA = rA >> 11, sA = rA & 2047;
    const int nBt = rB >> 11, sB = rB & 2047;
    const float* bias = (kind == 0) ? bq : (kind == 1) ? bk : bv;
    __nv_bfloat16* OH = (kind == 0) ? g_QH : (kind == 1) ? g_KH : g_VH;
    __nv_bfloat16* OL = (kind == 0) ? g_QL : (kind == 1) ? g_KL : g_VL;
    const size_t baseA = ((size_t)(nA  * NH + h) * SEQ + sA) * HD;
    const size_t baseB = ((size_t)(nBt * NH + h) * SEQ + sB) * HD;
    float pfA = 0.f, pfB = 0.f;
    if (kind != 2) { pfA = (float)positions[rA]; pfB = (float)positions[rB]; }

    #pragma unroll
    for (int n = 0; n < 4; ++n) {
        int d0 = wc + n * 8 + (lane & 3) * 2;       // even dim within head
        float b0 = bias[cW + d0], b1 = bias[cW + d0 + 1];
        float vA0 = o[n][0] + b0, vA1 = o[n][1] + b1;
        float vB0 = o[n][2] + b0, vB1 = o[n][3] + b1;
        if (kind != 2) {
            if (kind == 0) { vA0 *= 0.125f; vA1 *= 0.125f; vB0 *= 0.125f; vB1 *= 0.125f; }
            bool down = (kind == 1);
            rope_pair(vA0, vA1, d0, pfA, down);
            rope_pair(vB0, vB1, d0, pfB, down);
        }
        __nv_bfloat16 h0,h1,l0,l1;
        bf16split(vA0,h0,l0); bf16split(vA1,h1,l1);
        *(__nv_bfloat162*)&OH[baseA + d0] = __halves2bfloat162(h0,h1);
        *(__nv_bfloat162*)&OL[baseA + d0] = __halves2bfloat162(l0,l1);
        bf16split(vB0,h0,l0); bf16split(vB1,h1,l1);
        *(__nv_bfloat162*)&OH[baseB + d0] = __halves2bfloat162(h0,h1);
        *(__nv_bfloat162*)&OL[baseB + d0] = __halves2bfloat162(l0,l1);
    }
}

// ================= Kernel 2: tensor-core attention (R13, tiles now copy-only) =================
#define SO_QH   0
#define SO_QL   9216
#define SO_KH   18432
#define SO_KL   27648
#define SO_VTH  36864
#define SO_VTL  46080
#define SO_WH   55296
#define SO_WL   64512
#define SO_AST  73728            /* fp32 [col][row], stride 68 */
#define SO_WB   91136            /* fp32 [64] boundary weights */
#define SO_MS   91392            /* fp32 [64] mask tile */
#define ATTN_SMEM 91648

__global__ __launch_bounds__(256, 2) void attn_kernel(const float* __restrict__ mask)
{
    extern __shared__ char smc[];
    __nv_bfloat16* QH  = (__nv_bfloat16*)(smc + SO_QH);
    __nv_bfloat16* QL  = (__nv_bfloat16*)(smc + SO_QL);
    __nv_bfloat16* KH  = (__nv_bfloat16*)(smc + SO_KH);
    __nv_bfloat16* KL  = (__nv_bfloat16*)(smc + SO_KL);
    __nv_bfloat16* VTH = (__nv_bfloat16*)(smc + SO_VTH);
    __nv_bfloat16* VTL = (__nv_bfloat16*)(smc + SO_VTL);
    __nv_bfloat16* WH  = (__nv_bfloat16*)(smc + SO_WH);
    __nv_bfloat16* WL  = (__nv_bfloat16*)(smc + SO_WL);
    float* ASt = (float*)(smc + SO_AST);
    float* WB  = (float*)(smc + SO_WB);
    float* MS  = (float*)(smc + SO_MS);

    const unsigned sb = (unsigned)__cvta_generic_to_shared(smc);

    const int tid  = threadIdx.x;
    const int warp = tid >> 5;
    const int lane = tid & 31;
    const int wr   = (warp >> 1) * 16;
    const int wc   = (warp & 1) * 32;
    const int gh   = blockIdx.y;
    const int nb   = gh >> 3;
    const int hh   = gh & 7;
    const int rb   = (int)(gridDim.x - 1 - blockIdx.x);
    const int s0   = rb * 64;

    const __nv_bfloat16* QHg = g_QH + (size_t)gh * SEQ * HD;
    const __nv_bfloat16* QLg = g_QL + (size_t)gh * SEQ * HD;
    const __nv_bfloat16* KHg = g_KH + (size_t)gh * SEQ * HD;
    const __nv_bfloat16* KLg = g_KL + (size_t)gh * SEQ * HD;
    const __nv_bfloat16* VHg = g_VH + (size_t)gh * SEQ * HD;
    const __nv_bfloat16* VLg = g_VL + (size_t)gh * SEQ * HD;

    // ---- copy Q tile (bf16 hi/lo, no conversion) ----
    for (int it = tid; it < 512; it += 256) {
        int rr = it >> 3, f8 = (it & 7) * 8;
        *(uint4*)&QH[rr*72 + f8] = *(const uint4*)&QHg[(size_t)(s0+rr)*HD + f8];
        *(uint4*)&QL[rr*72 + f8] = *(const uint4*)&QLg[(size_t)(s0+rr)*HD + f8];
    }

    float cA = 0.0f;
    float cP = 1.0f;

    float o[4][4];
    #pragma unroll
    for (int n = 0; n < 4; ++n)
        #pragma unroll
        for (int r = 0; r < 4; ++r) o[n][r] = 0.0f;

    const unsigned aoffA = (unsigned)((lane & 15) * 72 + (lane >> 4) * 8);
    const unsigned boffB = (unsigned)((lane & 7) * 72 + ((lane >> 3) & 1) * 8);

    for (int jb = rb; jb >= 0; --jb) {
        const int lo = jb * 64;

        // ---- copy K tile; transpose-copy V tile ----
        for (int it = tid; it < 512; it += 256) {
            int rr = it >> 3, f8 = (it & 7) * 8;
            *(uint4*)&KH[rr*72 + f8] = *(const uint4*)&KHg[(size_t)(lo+rr)*HD + f8];
            *(uint4*)&KL[rr*72 + f8] = *(const uint4*)&KLg[(size_t)(lo+rr)*HD + f8];
        }
        {
            int t  = tid & 63;
            int dq = (tid >> 6) * 16;
            uint4 uh0 = *(const uint4*)&VHg[(size_t)(lo+t)*HD + dq];
            uint4 uh1 = *(const uint4*)&VHg[(size_t)(lo+t)*HD + dq + 8];
            uint4 ul0 = *(const uint4*)&VLg[(size_t)(lo+t)*HD + dq];
            uint4 ul1 = *(const uint4*)&VLg[(size_t)(lo+t)*HD + dq + 8];
            const __nv_bfloat16* ph0 = (const __nv_bfloat16*)&uh0;
            const __nv_bfloat16* ph1 = (const __nv_bfloat16*)&uh1;
            const __nv_bfloat16* pl0 = (const __nv_bfloat16*)&ul0;
            const __nv_bfloat16* pl1 = (const __nv_bfloat16*)&ul1;
            #pragma unroll
            for (int i = 0; i < 8; ++i) {
                VTH[(dq+i)*72 + t]   = ph0[i];
                VTH[(dq+8+i)*72 + t] = ph1[i];
                VTL[(dq+i)*72 + t]   = pl0[i];
                VTL[(dq+8+i)*72 + t] = pl1[i];
            }
        }
        if (tid < 64) MS[tid] = mask[nb * SEQ + lo + tid];
        __syncthreads();                               // (a)

        // ---- S = Q K^T via 3-pass bf16 split MMA ----
        float sc[4][4];
        #pragma unroll
        for (int n = 0; n < 4; ++n)
            #pragma unroll
            for (int r = 0; r < 4; ++r) sc[n][r] = 0.0f;

        #pragma unroll
        for (int kt = 0; kt < 4; ++kt) {
            unsigned aH0,aH1,aH2,aH3, aL0,aL1,aL2,aL3;
            unsigned abase = (aoffA + (unsigned)(kt * 16)) * 2u;
            ldsm4(aH0,aH1,aH2,aH3, sb + SO_QH + (unsigned)(wr * 144) + abase);
            ldsm4(aL0,aL1,aL2,aL3, sb + SO_QL + (unsigned)(wr * 144) + abase);
            #pragma unroll
            for (int n = 0; n < 4; ++n) {
                unsigned bH0,bH1,bL0,bL1;
                unsigned bbase = (boffB + (unsigned)(kt * 16)) * 2u + (unsigned)((wc + n * 8) * 144);
                ldsm2(bH0,bH1, sb + SO_KH + bbase);
                ldsm2(bL0,bL1, sb + SO_KL + bbase);
                mma16816(sc[n], aH0,aH1,aH2,aH3, bH0,bH1);
                mma16816(sc[n], aL0,aL1,aL2,aL3, bH0,bH1);
                mma16816(sc[n], aH0,aH1,aH2,aH3, bL0,bL1);
            }
        }

        // ---- sigmoid * mask * causal on fragments -> ASt[col][row] ----
        {
            const int lrow = wr + (lane >> 2);
            #pragma unroll
            for (int n = 0; n < 4; ++n) {
                const int lcol = wc + n * 8 + (lane & 3) * 2;
                float m0 = MS[lcol], m1 = MS[lcol + 1];
                #pragma unroll
                for (int r = 0; r < 4; ++r) {
                    int lr_ = lrow + (r >> 1) * 8;
                    int lc_ = lcol + (r & 1);
                    float mj = (r & 1) ? m1 : m0;
                    float a = 0.0f;
                    if (lo + lc_ <= s0 + lr_)
                        a = __fdividef(mj, 1.0f + __expf(-sc[n][r]));
                    ASt[lc_ * 68 + lr_] = a;
                }
            }
        }
        __syncthreads();                               // (b)

        // ---- per-row serial suffix-product scan, emit bf16 hi/lo weights ----
        if (tid < 64) {
            const int r = tid;
            float lA = cA, lP = cP;
            for (int c = 63; c >= 0; --c) {
                float a  = ASt[c * 68 + r];
                float Pn = ((1.0f - a) + EPSV) * lP;
                float w  = lA * Pn;
                if (c == 63) WB[r] = w;
                else {
                    __nv_bfloat16 h, l; bf16split(w, h, l);
                    WH[r * 72 + c + 1] = h; WL[r * 72 + c + 1] = l;
                }
                lA = a; lP = Pn;
            }
            float w0 = (jb == 0) ? lA : 0.0f;
            __nv_bfloat16 h, l; bf16split(w0, h, l);
            WH[r * 72] = h; WL[r * 72] = l;
            cA = lA; cP = lP;
        }
        __syncthreads();                               // (c)

        // ---- out += W * V via 3-pass bf16 split MMA ----
        #pragma unroll
        for (int kt = 0; kt < 4; ++kt) {
            unsigned aH0,aH1,aH2,aH3, aL0,aL1,aL2,aL3;
            unsigned abase = (aoffA + (unsigned)(kt * 16)) * 2u;
            ldsm4(aH0,aH1,aH2,aH3, sb + SO_WH + (unsigned)(wr * 144) + abase);
            ldsm4(aL0,aL1,aL2,aL3, sb + SO_WL + (unsigned)(wr * 144) + abase);
            #pragma unroll
            for (int n = 0; n < 4; ++n) {
                unsigned bH0,bH1,bL0,bL1;
                unsigned bbase = (boffB + (unsigned)(kt * 16)) * 2u + (unsigned)((wc + n * 8) * 144);
                ldsm2(bH0,bH1, sb + SO_VTH + bbase);
                ldsm2(bL0,bL1, sb + SO_VTL + bbase);
                mma16816(o[n], aH0,aH1,aH2,aH3, bH0,bH1);
                mma16816(o[n], aL0,aL1,aL2,aL3, bH0,bH1);
                mma16816(o[n], aH0,aH1,aH2,aH3, bL0,bL1);
            }
        }
        // boundary column: WB x V row lo+64 (reconstructed fp32 from hi+lo)
        if (jb < rb) {
            size_t vb = (size_t)(lo + 64) * HD;
            float wb0 = WB[wr + (lane >> 2)];
            float wb1 = WB[wr + (lane >> 2) + 8];
            #pragma unroll
            for (int n = 0; n < 4; ++n) {
                int d0 = wc + n * 8 + (lane & 3) * 2;
                __nv_bfloat162 hp = *(const __nv_bfloat162*)&VHg[vb + d0];
                __nv_bfloat162 lp = *(const __nv_bfloat162*)&VLg[vb + d0];
                float v0 = __bfloat162float(hp.x) + __bfloat162float(lp.x);
                float v1 = __bfloat162float(hp.y) + __bfloat162float(lp.y);
                o[n][0] = fmaf(wb0, v0, o[n][0]);
                o[n][1] = fmaf(wb0, v1, o[n][1]);
                o[n][2] = fmaf(wb1, v0, o[n][2]);
                o[n][3] = fmaf(wb1, v1, o[n][3]);
            }
        }
        __syncthreads();                               // (d)
    }

    // ---- write attended fragments as bf16 hi/lo to g_AH/g_AL ----
    {
        const int lrow = wr + (lane >> 2);
        #pragma unroll
        for (int n = 0; n < 4; ++n) {
            const int d0 = wc + n * 8 + (lane & 3) * 2;
            size_t bA = ((size_t)(nb * SEQ + s0 + lrow)) * DM + hh * HD + d0;
            size_t bB = ((size_t)(nb * SEQ + s0 + lrow + 8)) * DM + hh * HD + d0;
            __nv_bfloat16 h0,h1,l0,l1;
            bf16split(o[n][0],h0,l0); bf16split(o[n][1],h1,l1);
            *(__nv_bfloat162*)&g_AH[bA] = __halves2bfloat162(h0,h1);
            *(__nv_bfloat162*)&g_AL[bA] = __halves2bfloat162(l0,l1);
            bf16split(o[n][2],h0,l0); bf16split(o[n][3],h1,l1);
            *(__nv_bfloat162*)&g_AH[bB] = __halves2bfloat162(h0,h1);
            *(__nv_bfloat162*)&g_AL[bB] = __halves2bfloat162(l0,l1);
        }
    }
}

// ================= Kernel 3: output projection via 3-pass bf16-split MMA =================
__global__ __launch_bounds__(256) void oproj_mma(
    const float* __restrict__ bo, float* __restrict__ outp)
{
    __shared__ __nv_bfloat16 XHs[64*72], XLs[64*72], WHs[64*72], WLs[64*72];

    const int tid  = threadIdx.x;
    const int warp = tid >> 5;
    const int lane = tid & 31;
    const int wr   = (warp >> 1) * 16;
    const int wc   = (warp & 1) * 32;
    const int r0   = blockIdx.x * 64;
    const int c0   = blockIdx.y * 64;

    const __nv_bfloat16* WHg = g_WH + (size_t)3 * DM * DM;
    const __nv_bfloat16* WLg = g_WL + (size_t)3 * DM * DM;

    const unsigned sXH = (unsigned)__cvta_generic_to_shared(XHs);
    const unsigned sXL = (unsigned)__cvta_generic_to_shared(XLs);
    const unsigned sWH = (unsigned)__cvta_generic_to_shared(WHs);
    const unsigned sWL = (unsigned)__cvta_generic_to_shared(WLs);

    float o[4][4];
    #pragma unroll
    for (int n = 0; n < 4; ++n)
        #pragma unroll
        for (int r = 0; r < 4; ++r) o[n][r] = 0.0f;

    const unsigned aoffA = (unsigned)((lane & 15) * 72 + (lane >> 4) * 8);
    const unsigned boffB = (unsigned)((lane & 7) * 72 + ((lane >> 3) & 1) * 8);

    for (int kb = 0; kb < DM; kb += 64) {
        for (int it = tid; it < 512; it += 256) {
            int rr = it >> 3, f8 = (it & 7) * 8;
            *(uint4*)&XHs[rr*72 + f8] = *(const uint4*)&g_AH[(size_t)(r0+rr)*DM + kb + f8];
            *(uint4*)&XLs[rr*72 + f8] = *(const uint4*)&g_AL[(size_t)(r0+rr)*DM + kb + f8];
            *(uint4*)&WHs[rr*72 + f8] = *(const uint4*)&WHg[(size_t)(c0+rr)*DM + kb + f8];
            *(uint4*)&WLs[rr*72 + f8] = *(const uint4*)&WLg[(size_t)(c0+rr)*DM + kb + f8];
        }
        __syncthreads();

        #pragma unroll
        for (int kt = 0; kt < 4; ++kt) {
            unsigned aH0,aH1,aH2,aH3, aL0,aL1,aL2,aL3;
            unsigned abase = (aoffA + (unsigned)(kt * 16)) * 2u + (unsigned)(wr * 144);
            ldsm4(aH0,aH1,aH2,aH3, sXH + abase);
            ldsm4(aL0,aL1,aL2,aL3, sXL + abase);
            #pragma unroll
            for (int n = 0; n < 4; ++n) {
                unsigned bH0,bH1,bL0,bL1;
                unsigned bbase = (boffB + (unsigned)(kt * 16)) * 2u + (unsigned)((wc + n * 8) * 144);
                ldsm2(bH0,bH1, sWH + bbase);
                ldsm2(bL0,bL1, sWL + bbase);
                mma16816(o[n], aH0,aH1,aH2,aH3, bH0,bH1);
                mma16816(o[n], aL0,aL1,aL2,aL3, bH0,bH1);
                mma16816(o[n], aH0,aH1,aH2,aH3, bL0,bL1);
            }
        }
        __syncthreads();
    }

    const int lrow = wr + (lane >> 2);
    const int rA = r0 + lrow, rB = rA + 8;
    #pragma unroll
    for (int n = 0; n < 4; ++n) {
        int d0 = wc + n * 8 + (lane & 3) * 2;
        float b0 = bo[c0 + d0], b1 = bo[c0 + d0 + 1];
        *(float2*)&outp[(size_t)rA * DM + c0 + d0] = make_float2(o[n][0] + b0, o[n][1] + b1);
        *(float2*)&outp[(size_t)rB * DM + c0 + d0] = make_float2(o[n][2] + b0, o[n][3] + b1);
    }
}

// ================= host launcher =================
extern "C" void kernel_launch(void* const* d_in, const int* in_sizes, int n_in,
                              void* d_out, int out_size)
{
    const float* seqp = nullptr;
    const float* maskp = nullptr;
    const int*   posp = nullptr;
    const float* W[4] = {nullptr, nullptr, nullptr, nullptr};
    const float* B[4] = {nullptr, nullptr, nullptr, nullptr};
    int nw = 0, nbb = 0, n4096 = 0;
    for (int i = 0; i < n_in; ++i) {
        int sz = in_sizes[i];
        if (sz == NB * SEQ * DM) {
            seqp = (const float*)d_in[i];
        } else if (sz == DM * DM) {
            if (nw < 4) W[nw++] = (const float*)d_in[i];
        } else if (sz == DM) {
            if (nbb < 4) B[nbb++] = (const float*)d_in[i];
        } else if (sz == NB * SEQ) {
            if (n4096 == 0) maskp = (const float*)d_in[i];
            else            posp  = (const int*)d_in[i];
            ++n4096;
        }
    }

    cudaFuncSetAttribute(attn_kernel, cudaFuncAttributeMaxDynamicSharedMemorySize, ATTN_SMEM);

    convert_kernel<<<(X_F4 + 4 * W_F4) / 256, 256>>>(seqp, W[0], W[1], W[2], W[3]);
    qkv_mma<<<dim3(64, 24), 256>>>(B[0], B[1], B[2], posp);
    attn_kernel<<<dim3(32, 16), 256, ATTN_SMEM>>>(maskp);
    oproj_mma<<<dim3(64, 8), 256>>>(B[3], (float*)d_out);
}

// round 15
// speedup vs baseline: 3.3755x; 1.0514x over previous
#include <cuda_runtime.h>
#include <cuda_bf16.h>

#define NB   2
#define SEQ  2048
#define DM   512
#define NH   8
#define HD   64
#define GHD  (NB*NH)      /* 16 global heads */
#define EPSV 1e-8f

// ---------------- tensor-core helpers (proven R13/R14) ----------------
__device__ __forceinline__ void ldsm4(unsigned& r0, unsigned& r1, unsigned& r2, unsigned& r3, unsigned addr) {
    asm volatile("ldmatrix.sync.aligned.m8n8.x4.shared.b16 {%0,%1,%2,%3}, [%4];"
        : "=r"(r0), "=r"(r1), "=r"(r2), "=r"(r3) : "r"(addr));
}
__device__ __forceinline__ void ldsm2(unsigned& r0, unsigned& r1, unsigned addr) {
    asm volatile("ldmatrix.sync.aligned.m8n8.x2.shared.b16 {%0,%1}, [%2];"
        : "=r"(r0), "=r"(r1) : "r"(addr));
}
__device__ __forceinline__ void ldsm2t(unsigned& r0, unsigned& r1, unsigned addr) {
    asm volatile("ldmatrix.sync.aligned.m8n8.x2.trans.shared.b16 {%0,%1}, [%2];"
        : "=r"(r0), "=r"(r1) : "r"(addr));
}
__device__ __forceinline__ void mma16816(float* c, unsigned a0, unsigned a1, unsigned a2, unsigned a3,
                                         unsigned b0, unsigned b1) {
    asm volatile("mma.sync.aligned.m16n8k16.row.col.f32.bf16.bf16.f32 "
        "{%0,%1,%2,%3}, {%4,%5,%6,%7}, {%8,%9}, {%0,%1,%2,%3};"
        : "+f"(c[0]), "+f"(c[1]), "+f"(c[2]), "+f"(c[3])
        : "r"(a0), "r"(a1), "r"(a2), "r"(a3), "r"(b0), "r"(b1));
}
__device__ __forceinline__ void bf16split(float x, __nv_bfloat16& h, __nv_bfloat16& l) {
    h = __float2bfloat16(x);
    l = __float2bfloat16(x - __bfloat162float(h));
}
__device__ __forceinline__ void cp16(unsigned dst, const void* src) {
    asm volatile("cp.async.cg.shared.global [%0], [%1], 16;" :: "r"(dst), "l"(src));
}
#define CP_COMMIT() asm volatile("cp.async.commit_group;" ::: "memory")
#define CP_WAIT1()  asm volatile("cp.async.wait_group 1;"  ::: "memory")

// ---------------- scratch (static device globals; all bf16 hi/lo pairs) ----------------
__device__ __nv_bfloat16 g_XH[NB*SEQ*DM], g_XL[NB*SEQ*DM];   // sequence
__device__ __nv_bfloat16 g_WH[4*DM*DM],  g_WL[4*DM*DM];      // Wq,Wk,Wv,Wo
__device__ __nv_bfloat16 g_QH[GHD*SEQ*HD], g_QL[GHD*SEQ*HD];
__device__ __nv_bfloat16 g_KH[GHD*SEQ*HD], g_KL[GHD*SEQ*HD];
__device__ __nv_bfloat16 g_VH[GHD*SEQ*HD], g_VL[GHD*SEQ*HD];
__device__ __nv_bfloat16 g_AH[NB*SEQ*DM],  g_AL[NB*SEQ*DM];  // attended

// ================= xPos rotary helper =================
__device__ __forceinline__ void rope_pair(float& x1, float& x2, int deven, float pf, bool down)
{
    float sv   = ((float)deven + 25.6f) * (1.0f / 89.6f);
    float invf = powf(10000.0f, -(float)deven * (1.0f / 64.0f));
    float th   = pf * invf;
    float sn, cs;
    sincosf(th, &sn, &cs);
    float sc = powf(sv, pf * (1.0f / 512.0f));
    if (down) sc = 1.0f / sc;
    float y1 = (x1 * cs - x2 * sn) * sc;
    float y2 = (x2 * cs + x1 * sn) * sc;
    x1 = y1; x2 = y2;
}

// ================= Kernel 0: one-shot fp32 -> bf16 hi/lo conversion =================
#define X_F4 ((NB*SEQ*DM)/4)     /* 524288 */
#define W_F4 ((DM*DM)/4)         /* 65536 = 2^16 */

__global__ __launch_bounds__(256) void convert_kernel(
    const float* __restrict__ X,
    const float* __restrict__ Wq, const float* __restrict__ Wk,
    const float* __restrict__ Wv, const float* __restrict__ Wo)
{
    int gid = blockIdx.x * 256 + threadIdx.x;          // float4 index
    const float* src; __nv_bfloat16 *dh, *dl; int off;
    if (gid < X_F4) {
        src = X; dh = g_XH; dl = g_XL; off = gid;
    } else {
        int t = gid - X_F4;
        int w = t >> 16;                // 65536 float4 per weight
        off   = t & (W_F4 - 1);
        src = (w == 0) ? Wq : (w == 1) ? Wk : (w == 2) ? Wv : Wo;
        dh = g_WH + w * DM * DM; dl = g_WL + w * DM * DM;
    }
    float4 v = ((const float4*)src)[off];
    __nv_bfloat16 h0,h1,h2,h3,l0,l1,l2,l3;
    bf16split(v.x,h0,l0); bf16split(v.y,h1,l1); bf16split(v.z,h2,l2); bf16split(v.w,h3,l3);
    __nv_bfloat162* ph = (__nv_bfloat162*)(dh + off * 4);
    __nv_bfloat162* pl = (__nv_bfloat162*)(dl + off * 4);
    ph[0] = __halves2bfloat162(h0,h1); ph[1] = __halves2bfloat162(h2,h3);
    pl[0] = __halves2bfloat162(l0,l1); pl[1] = __halves2bfloat162(l2,l3);
}

// ================= Kernel 1: QKV projection via 3-pass bf16-split MMA (R14-proven) =================
__global__ __launch_bounds__(256) void qkv_mma(
    const float* __restrict__ bq, const float* __restrict__ bk, const float* __restrict__ bv,
    const int* __restrict__ positions)
{
    __shared__ __nv_bfloat16 XHs[64*72], XLs[64*72], WHs[64*72], WLs[64*72];

    const int tid  = threadIdx.x;
    const int warp = tid >> 5;
    const int lane = tid & 31;
    const int wr   = (warp >> 1) * 16;
    const int wc   = (warp & 1) * 32;
    const int r0   = blockIdx.x * 64;
    const int c0   = blockIdx.y * 64;
    const int kind = c0 / DM;
    const int cW   = c0 % DM;
    const int h    = cW >> 6;

    const __nv_bfloat16* WHg = g_WH + (size_t)kind * DM * DM;
    const __nv_bfloat16* WLg = g_WL + (size_t)kind * DM * DM;

    const unsigned sXH = (unsigned)__cvta_generic_to_shared(XHs);
    const unsigned sXL = (unsigned)__cvta_generic_to_shared(XLs);
    const unsigned sWH = (unsigned)__cvta_generic_to_shared(WHs);
    const unsigned sWL = (unsigned)__cvta_generic_to_shared(WLs);

    float o[4][4];
    #pragma unroll
    for (int n = 0; n < 4; ++n)
        #pragma unroll
        for (int r = 0; r < 4; ++r) o[n][r] = 0.0f;

    const unsigned aoffA = (unsigned)((lane & 15) * 72 + (lane >> 4) * 8);
    const unsigned boffB = (unsigned)((lane & 7) * 72 + ((lane >> 3) & 1) * 8);

    for (int kb = 0; kb < DM; kb += 64) {
        for (int it = tid; it < 512; it += 256) {
            int rr = it >> 3, f8 = (it & 7) * 8;
            *(uint4*)&XHs[rr*72 + f8] = *(const uint4*)&g_XH[(size_t)(r0+rr)*DM + kb + f8];
            *(uint4*)&XLs[rr*72 + f8] = *(const uint4*)&g_XL[(size_t)(r0+rr)*DM + kb + f8];
            *(uint4*)&WHs[rr*72 + f8] = *(const uint4*)&WHg[(size_t)(cW+rr)*DM + kb + f8];
            *(uint4*)&WLs[rr*72 + f8] = *(const uint4*)&WLg[(size_t)(cW+rr)*DM + kb + f8];
        }
        __syncthreads();

        #pragma unroll
        for (int kt = 0; kt < 4; ++kt) {
            unsigned aH0,aH1,aH2,aH3, aL0,aL1,aL2,aL3;
            unsigned abase = (aoffA + (unsigned)(kt * 16)) * 2u + (unsigned)(wr * 144);
            ldsm4(aH0,aH1,aH2,aH3, sXH + abase);
            ldsm4(aL0,aL1,aL2,aL3, sXL + abase);
            #pragma unroll
            for (int n = 0; n < 4; ++n) {
                unsigned bH0,bH1,bL0,bL1;
                unsigned bbase = (boffB + (unsigned)(kt * 16)) * 2u + (unsigned)((wc + n * 8) * 144);
                ldsm2(bH0,bH1, sWH + bbase);
                ldsm2(bL0,bL1, sWL + bbase);
                mma16816(o[n], aH0,aH1,aH2,aH3, bH0,bH1);
                mma16816(o[n], aL0,aL1,aL2,aL3, bH0,bH1);
                mma16816(o[n], aH0,aH1,aH2,aH3, bL0,bL1);
            }
        }
        __syncthreads();
    }

    const int lrow = wr + (lane >> 2);
    const int rA = r0 + lrow, rB = rA + 8;
    const int nA = rA >> 11, sA = rA & 2047;
    const int nBt = rB >> 11, sB = rB & 2047;
    const float* bias = (kind == 0) ? bq : (kind == 1) ? bk : bv;
    __nv_bfloat16* OH = (kind == 0) ? g_QH : (kind == 1) ? g_KH : g_VH;
    __nv_bfloat16* OL = (kind == 0) ? g_QL : (kind == 1) ? g_KL : g_VL;
    const size_t baseA = ((size_t)(nA  * NH + h) * SEQ + sA) * HD;
    const size_t baseB = ((size_t)(nBt * NH + h) * SEQ + sB) * HD;
    float pfA = 0.f, pfB = 0.f;
    if (kind != 2) { pfA = (float)positions[rA]; pfB = (float)positions[rB]; }

    #pragma unroll
    for (int n = 0; n < 4; ++n) {
        int d0 = wc + n * 8 + (lane & 3) * 2;
        float b0 = bias[cW + d0], b1 = bias[cW + d0 + 1];
        float vA0 = o[n][0] + b0, vA1 = o[n][1] + b1;
        float vB0 = o[n][2] + b0, vB1 = o[n][3] + b1;
        if (kind != 2) {
            if (kind == 0) { vA0 *= 0.125f; vA1 *= 0.125f; vB0 *= 0.125f; vB1 *= 0.125f; }
            bool down = (kind == 1);
            rope_pair(vA0, vA1, d0, pfA, down);
            rope_pair(vB0, vB1, d0, pfB, down);
        }
        __nv_bfloat16 h0,h1,l0,l1;
        bf16split(vA0,h0,l0); bf16split(vA1,h1,l1);
        *(__nv_bfloat162*)&OH[baseA + d0] = __halves2bfloat162(h0,h1);
        *(__nv_bfloat162*)&OL[baseA + d0] = __halves2bfloat162(l0,l1);
        bf16split(vB0,h0,l0); bf16split(vB1,h1,l1);
        *(__nv_bfloat162*)&OH[baseB + d0] = __halves2bfloat162(h0,h1);
        *(__nv_bfloat162*)&OL[baseB + d0] = __halves2bfloat162(l0,l1);
    }
}

// ================= Kernel 2: tensor-core attention (trans-V, cp.async, K double-buffer) =================
#define SO_QH   0
#define SO_QL   9216
#define SO_K0   18432            /* KH buf0; KL at +9216 */
#define SO_K1   36864            /* KH buf1; KL at +9216 */
#define SO_VH   55296            /* V row-major [t][d], stride 72 */
#define SO_VL   64512
#define SO_WHo  73728            /* weights bf16 hi, [row][col] stride 72 */
#define SO_WLo  82944
#define SO_AS   92160            /* fp32 sigmoid A, [row][col] stride 68 */
#define SO_WB   109568           /* fp32 [64] boundary weights */
#define SO_MS   109824           /* fp32 [64] mask tile */
#define ATTN_SMEM 110080

__global__ __launch_bounds__(256, 2) void attn_kernel(const float* __restrict__ mask)
{
    extern __shared__ char smc[];
    __nv_bfloat16* QH  = (__nv_bfloat16*)(smc + SO_QH);
    __nv_bfloat16* QL  = (__nv_bfloat16*)(smc + SO_QL);
    __nv_bfloat16* WHs = (__nv_bfloat16*)(smc + SO_WHo);
    __nv_bfloat16* WLs = (__nv_bfloat16*)(smc + SO_WLo);
    float* AS  = (float*)(smc + SO_AS);
    float* WB  = (float*)(smc + SO_WB);
    float* MS  = (float*)(smc + SO_MS);

    const unsigned sb = (unsigned)__cvta_generic_to_shared(smc);

    const int tid  = threadIdx.x;
    const int warp = tid >> 5;
    const int lane = tid & 31;
    const int wr   = (warp >> 1) * 16;
    const int wc   = (warp & 1) * 32;
    const int gh   = blockIdx.y;
    const int nb   = gh >> 3;
    const int hh   = gh & 7;
    const int rb   = (int)(gridDim.x - 1 - blockIdx.x);   // heavy blocks first
    const int s0   = rb * 64;

    const __nv_bfloat16* QHg = g_QH + (size_t)gh * SEQ * HD;
    const __nv_bfloat16* QLg = g_QL + (size_t)gh * SEQ * HD;
    const __nv_bfloat16* KHg = g_KH + (size_t)gh * SEQ * HD;
    const __nv_bfloat16* KLg = g_KL + (size_t)gh * SEQ * HD;
    const __nv_bfloat16* VHg = g_VH + (size_t)gh * SEQ * HD;
    const __nv_bfloat16* VLg = g_VL + (size_t)gh * SEQ * HD;

    // ---- copy Q tile (sync, once) ----
    for (int it = tid; it < 512; it += 256) {
        int rr = it >> 3, f8 = (it & 7) * 8;
        *(uint4*)&QH[rr*72 + f8] = *(const uint4*)&QHg[(size_t)(s0+rr)*HD + f8];
        *(uint4*)&QL[rr*72 + f8] = *(const uint4*)&QLg[(size_t)(s0+rr)*HD + f8];
    }

    // ---- prefetch K(rb) into buf0 (group) ----
    {
        const int lo0 = rb * 64;
        #pragma unroll
        for (int q = 0; q < 2; ++q) {
            int it = tid + q * 256;
            int rr = it >> 3, f8 = (it & 7) * 8;
            unsigned d = (unsigned)SO_K0 + (unsigned)((rr * 72 + f8) * 2);
            cp16(sb + d,        &KHg[(size_t)(lo0 + rr) * HD + f8]);
            cp16(sb + d + 9216, &KLg[(size_t)(lo0 + rr) * HD + f8]);
        }
    }
    CP_COMMIT();

    float cA = 0.0f;
    float cP = 1.0f;

    float o[4][4];
    #pragma unroll
    for (int n = 0; n < 4; ++n)
        #pragma unroll
        for (int r = 0; r < 4; ++r) o[n][r] = 0.0f;

    const unsigned aoffA = (unsigned)((lane & 15) * 72 + (lane >> 4) * 8);
    const unsigned boffB = (unsigned)((lane & 7) * 72 + ((lane >> 3) & 1) * 8);
    const unsigned toffB = (unsigned)((lane & 15) * 144);   // trans-V row address

    for (int jb = rb; jb >= 0; --jb) {
        const int lo = jb * 64;
        const unsigned curK = ((rb - jb) & 1) ? (unsigned)SO_K1 : (unsigned)SO_K0;
        const unsigned nxtK = ((rb - jb) & 1) ? (unsigned)SO_K0 : (unsigned)SO_K1;

        // group A: V(jb) row-major + mask tile
        #pragma unroll
        for (int q = 0; q < 2; ++q) {
            int it = tid + q * 256;
            int rr = it >> 3, f8 = (it & 7) * 8;
            unsigned d = (unsigned)((rr * 72 + f8) * 2);
            cp16(sb + SO_VH + d, &VHg[(size_t)(lo + rr) * HD + f8]);
            cp16(sb + SO_VL + d, &VLg[(size_t)(lo + rr) * HD + f8]);
        }
        if (tid < 16) cp16(sb + SO_MS + (unsigned)(tid * 16), &mask[(size_t)nb * SEQ + lo + tid * 4]);
        CP_COMMIT();
        // group B: K(jb-1) into alternate buffer (flies through this tile's compute)
        if (jb > 0) {
            #pragma unroll
            for (int q = 0; q < 2; ++q) {
                int it = tid + q * 256;
                int rr = it >> 3, f8 = (it & 7) * 8;
                unsigned d = nxtK + (unsigned)((rr * 72 + f8) * 2);
                cp16(sb + d,        &KHg[(size_t)(lo - 64 + rr) * HD + f8]);
                cp16(sb + d + 9216, &KLg[(size_t)(lo - 64 + rr) * HD + f8]);
            }
        }
        CP_COMMIT();
        CP_WAIT1();                 // completes K(jb) and V(jb)+MS; leaves K(jb-1) in flight
        __syncthreads();            // (a)

        // ---- S = Q K^T via 3-pass bf16 split MMA ----
        float sc[4][4];
        #pragma unroll
        for (int n = 0; n < 4; ++n)
            #pragma unroll
            for (int r = 0; r < 4; ++r) sc[n][r] = 0.0f;

        #pragma unroll
        for (int kt = 0; kt < 4; ++kt) {
            unsigned aH0,aH1,aH2,aH3, aL0,aL1,aL2,aL3;
            unsigned abase = (aoffA + (unsigned)(kt * 16)) * 2u;
            ldsm4(aH0,aH1,aH2,aH3, sb + SO_QH + (unsigned)(wr * 144) + abase);
            ldsm4(aL0,aL1,aL2,aL3, sb + SO_QL + (unsigned)(wr * 144) + abase);
            #pragma unroll
            for (int n = 0; n < 4; ++n) {
                unsigned bH0,bH1,bL0,bL1;
                unsigned bbase = (boffB + (unsigned)(kt * 16)) * 2u + (unsigned)((wc + n * 8) * 144);
                ldsm2(bH0,bH1, sb + curK + bbase);
                ldsm2(bL0,bL1, sb + curK + 9216u + bbase);
                mma16816(sc[n], aH0,aH1,aH2,aH3, bH0,bH1);
                mma16816(sc[n], aL0,aL1,aL2,aL3, bH0,bH1);
                mma16816(sc[n], aH0,aH1,aH2,aH3, bL0,bL1);
            }
        }

        // ---- sigmoid * mask * causal on fragments -> AS[row][col] (float2 stores) ----
        {
            const int lrow = wr + (lane >> 2);
            #pragma unroll
            for (int n = 0; n < 4; ++n) {
                const int lc = wc + n * 8 + (lane & 3) * 2;
                float m0 = MS[lc], m1 = MS[lc + 1];
                float a0 = 0.f, a1 = 0.f, a2 = 0.f, a3 = 0.f;
                if (lo + lc     <= s0 + lrow)     a0 = __fdividef(m0, 1.0f + __expf(-sc[n][0]));
                if (lo + lc + 1 <= s0 + lrow)     a1 = __fdividef(m1, 1.0f + __expf(-sc[n][1]));
                if (lo + lc     <= s0 + lrow + 8) a2 = __fdividef(m0, 1.0f + __expf(-sc[n][2]));
                if (lo + lc + 1 <= s0 + lrow + 8) a3 = __fdividef(m1, 1.0f + __expf(-sc[n][3]));
                *(float2*)&AS[lrow * 68 + lc]       = make_float2(a0, a1);
                *(float2*)&AS[(lrow + 8) * 68 + lc] = make_float2(a2, a3);
            }
        }
        __syncthreads();            // (b)

        // ---- per-row serial suffix-product scan, float4-batched, fully unrolled ----
        if (tid < 64) {
            const int r = tid;
            float lA = cA, lP = cP;
            #pragma unroll
            for (int cc = 60; cc >= 0; cc -= 4) {
                float4 a4 = *(const float4*)&AS[r * 68 + cc];
                {   // c = cc+3
                    float Pn = ((1.0f - a4.w) + EPSV) * lP; float w = lA * Pn;
                    if (cc == 60) WB[r] = w;
                    else { __nv_bfloat16 h,l; bf16split(w,h,l); WHs[r*72+cc+4]=h; WLs[r*72+cc+4]=l; }
                    lA = a4.w; lP = Pn;
                }
                {   // c = cc+2
                    float Pn = ((1.0f - a4.z) + EPSV) * lP; float w = lA * Pn;
                    __nv_bfloat16 h,l; bf16split(w,h,l); WHs[r*72+cc+3]=h; WLs[r*72+cc+3]=l;
                    lA = a4.z; lP = Pn;
                }
                {   // c = cc+1
                    float Pn = ((1.0f - a4.y) + EPSV) * lP; float w = lA * Pn;
                    __nv_bfloat16 h,l; bf16split(w,h,l); WHs[r*72+cc+2]=h; WLs[r*72+cc+2]=l;
                    lA = a4.y; lP = Pn;
                }
                {   // c = cc
                    float Pn = ((1.0f - a4.x) + EPSV) * lP; float w = lA * Pn;
                    __nv_bfloat16 h,l; bf16split(w,h,l); WHs[r*72+cc+1]=h; WLs[r*72+cc+1]=l;
                    lA = a4.x; lP = Pn;
                }
            }
            float w0 = (jb == 0) ? lA : 0.0f;
            __nv_bfloat16 h, l; bf16split(w0, h, l);
            WHs[r * 72] = h; WLs[r * 72] = l;
            cA = lA; cP = lP;
        }
        __syncthreads();            // (c)

        // ---- out += W * V via 3-pass bf16 split MMA (V row-major + ldmatrix.trans) ----
        #pragma unroll
        for (int kt = 0; kt < 4; ++kt) {
            unsigned aH0,aH1,aH2,aH3, aL0,aL1,aL2,aL3;
            unsigned abase = (aoffA + (unsigned)(kt * 16)) * 2u;
            ldsm4(aH0,aH1,aH2,aH3, sb + SO_WHo + (unsigned)(wr * 144) + abase);
            ldsm4(aL0,aL1,aL2,aL3, sb + SO_WLo + (unsigned)(wr * 144) + abase);
            unsigned tb = (unsigned)(kt * 16 * 144) + toffB;
            #pragma unroll
            for (int n = 0; n < 4; ++n) {
                unsigned bH0,bH1,bL0,bL1;
                unsigned bbase = tb + (unsigned)((wc + n * 8) * 2);
                ldsm2t(bH0,bH1, sb + SO_VH + bbase);
                ldsm2t(bL0,bL1, sb + SO_VL + bbase);
                mma16816(o[n], aH0,aH1,aH2,aH3, bH0,bH1);
                mma16816(o[n], aL0,aL1,aL2,aL3, bH0,bH1);
                mma16816(o[n], aH0,aH1,aH2,aH3, bL0,bL1);
            }
        }
        // boundary column: WB x V row lo+64 (reconstructed fp32 from hi+lo globals)
        if (jb < rb) {
            size_t vb = (size_t)(lo + 64) * HD;
            float wb0 = WB[wr + (lane >> 2)];
            float wb1 = WB[wr + (lane >> 2) + 8];
            #pragma unroll
            for (int n = 0; n < 4; ++n) {
                int d0 = wc + n * 8 + (lane & 3) * 2;
                __nv_bfloat162 hp = *(const __nv_bfloat162*)&VHg[vb + d0];
                __nv_bfloat162 lp = *(const __nv_bfloat162*)&VLg[vb + d0];
                float v0 = __bfloat162float(hp.x) + __bfloat162float(lp.x);
                float v1 = __bfloat162float(hp.y) + __bfloat162float(lp.y);
                o[n][0] = fmaf(wb0, v0, o[n][0]);
                o[n][1] = fmaf(wb0, v1, o[n][1]);
                o[n][2] = fmaf(wb1, v0, o[n][2]);
                o[n][3] = fmaf(wb1, v1, o[n][3]);
            }
        }
        __syncthreads();            // (d)
    }

    // ---- write attended fragments as bf16 hi/lo to g_AH/g_AL ----
    {
        const int lrow = wr + (lane >> 2);
        #pragma unroll
        for (int n = 0; n < 4; ++n) {
            const int d0 = wc + n * 8 + (lane & 3) * 2;
            size_t bA = ((size_t)(nb * SEQ + s0 + lrow)) * DM + hh * HD + d0;
            size_t bB = ((size_t)(nb * SEQ + s0 + lrow + 8)) * DM + hh * HD + d0;
            __nv_bfloat16 h0,h1,l0,l1;
            bf16split(o[n][0],h0,l0); bf16split(o[n][1],h1,l1);
            *(__nv_bfloat162*)&g_AH[bA] = __halves2bfloat162(h0,h1);
            *(__nv_bfloat162*)&g_AL[bA] = __halves2bfloat162(l0,l1);
            bf16split(o[n][2],h0,l0); bf16split(o[n][3],h1,l1);
            *(__nv_bfloat162*)&g_AH[bB] = __halves2bfloat162(h0,h1);
            *(__nv_bfloat162*)&g_AL[bB] = __halves2bfloat162(l0,l1);
        }
    }
}

// ================= Kernel 3: output projection via 3-pass bf16-split MMA (R14-proven) =================
__global__ __launch_bounds__(256) void oproj_mma(
    const float* __restrict__ bo, float* __restrict__ outp)
{
    __shared__ __nv_bfloat16 XHs[64*72], XLs[64*72], WHs[64*72], WLs[64*72];

    const int tid  = threadIdx.x;
    const int warp = tid >> 5;
    const int lane = tid & 31;
    const int wr   = (warp >> 1) * 16;
    const int wc   = (warp & 1) * 32;
    const int r0   = blockIdx.x * 64;
    const int c0   = blockIdx.y * 64;

    const __nv_bfloat16* WHg = g_WH + (size_t)3 * DM * DM;
    const __nv_bfloat16* WLg = g_WL + (size_t)3 * DM * DM;

    const unsigned sXH = (unsigned)__cvta_generic_to_shared(XHs);
    const unsigned sXL = (unsigned)__cvta_generic_to_shared(XLs);
    const unsigned sWH = (unsigned)__cvta_generic_to_shared(WHs);
    const unsigned sWL = (unsigned)__cvta_generic_to_shared(WLs);

    float o[4][4];
    #pragma unroll
    for (int n = 0; n < 4; ++n)
        #pragma unroll
        for (int r = 0; r < 4; ++r) o[n][r] = 0.0f;

    const unsigned aoffA = (unsigned)((lane & 15) * 72 + (lane >> 4) * 8);
    const unsigned boffB = (unsigned)((lane & 7) * 72 + ((lane >> 3) & 1) * 8);

    for (int kb = 0; kb < DM; kb += 64) {
        for (int it = tid; it < 512; it += 256) {
            int rr = it >> 3, f8 = (it & 7) * 8;
            *(uint4*)&XHs[rr*72 + f8] = *(const uint4*)&g_AH[(size_t)(r0+rr)*DM + kb + f8];
            *(uint4*)&XLs[rr*72 + f8] = *(const uint4*)&g_AL[(size_t)(r0+rr)*DM + kb + f8];
            *(uint4*)&WHs[rr*72 + f8] = *(const uint4*)&WHg[(size_t)(c0+rr)*DM + kb + f8];
            *(uint4*)&WLs[rr*72 + f8] = *(const uint4*)&WLg[(size_t)(c0+rr)*DM + kb + f8];
        }
        __syncthreads();

        #pragma unroll
        for (int kt = 0; kt < 4; ++kt) {
            unsigned aH0,aH1,aH2,aH3, aL0,aL1,aL2,aL3;
            unsigned abase = (aoffA + (unsigned)(kt * 16)) * 2u + (unsigned)(wr * 144);
            ldsm4(aH0,aH1,aH2,aH3, sXH + abase);
            ldsm4(aL0,aL1,aL2,aL3, sXL + abase);
            #pragma unroll
            for (int n = 0; n < 4; ++n) {
                unsigned bH0,bH1,bL0,bL1;
                unsigned bbase = (boffB + (unsigned)(kt * 16)) * 2u + (unsigned)((wc + n * 8) * 144);
                ldsm2(bH0,bH1, sWH + bbase);
                ldsm2(bL0,bL1, sWL + bbase);
                mma16816(o[n], aH0,aH1,aH2,aH3, bH0,bH1);
                mma16816(o[n], aL0,aL1,aL2,aL3, bH0,bH1);
                mma16816(o[n], aH0,aH1,aH2,aH3, bL0,bL1);
            }
        }
        __syncthreads();
    }

    const int lrow = wr + (lane >> 2);
    const int rA = r0 + lrow, rB = rA + 8;
    #pragma unroll
    for (int n = 0; n < 4; ++n) {
        int d0 = wc + n * 8 + (lane & 3) * 2;
        float b0 = bo[c0 + d0], b1 = bo[c0 + d0 + 1];
        *(float2*)&outp[(size_t)rA * DM + c0 + d0] = make_float2(o[n][0] + b0, o[n][1] + b1);
        *(float2*)&outp[(size_t)rB * DM + c0 + d0] = make_float2(o[n][2] + b0, o[n][3] + b1);
    }
}

// ================= host launcher =================
extern "C" void kernel_launch(void* const* d_in, const int* in_sizes, int n_in,
                              void* d_out, int out_size)
{
    const float* seqp = nullptr;
    const float* maskp = nullptr;
    const int*   posp = nullptr;
    const float* W[4] = {nullptr, nullptr, nullptr, nullptr};
    const float* B[4] = {nullptr, nullptr, nullptr, nullptr};
    int nw = 0, nbb = 0, n4096 = 0;
    for (int i = 0; i < n_in; ++i) {
        int sz = in_sizes[i];
        if (sz == NB * SEQ * DM) {
            seqp = (const float*)d_in[i];
        } else if (sz == DM * DM) {
            if (nw < 4) W[nw++] = (const float*)d_in[i];
        } else if (sz == DM) {
            if (nbb < 4) B[nbb++] = (const float*)d_in[i];
        } else if (sz == NB * SEQ) {
            if (n4096 == 0) maskp = (const float*)d_in[i];
            else            posp  = (const int*)d_in[i];
            ++n4096;
        }
    }

    cudaFuncSetAttribute(attn_kernel, cudaFuncAttributeMaxDynamicSharedMemorySize, ATTN_SMEM);

    convert_kernel<<<(X_F4 + 4 * W_F4) / 256, 256>>>(seqp, W[0], W[1], W[2], W[3]);
    qkv_mma<<<dim3(64, 24), 256>>>(B[0], B[1], B[2], posp);
    attn_kernel<<<dim3(32, 16), 256, ATTN_SMEM>>>(maskp);
    oproj_mma<<<dim3(64, 8), 256>>>(B[3], (float*)d_out);
}

// round 16
// speedup vs baseline: 5.1243x; 1.5181x over previous
#include <cuda_runtime.h>
#include <cuda_bf16.h>

#define NB   2
#define SEQ  2048
#define DM   512
#define NH   8
#define HD   64
#define GHD  (NB*NH)      /* 16 global heads */
#define EPSV 1e-8f

// ---------------- tensor-core helpers ----------------
__device__ __forceinline__ void ldsm4(unsigned& r0, unsigned& r1, unsigned& r2, unsigned& r3, unsigned addr) {
    asm volatile("ldmatrix.sync.aligned.m8n8.x4.shared.b16 {%0,%1,%2,%3}, [%4];"
        : "=r"(r0), "=r"(r1), "=r"(r2), "=r"(r3) : "r"(addr));
}
__device__ __forceinline__ void ldsm4t(unsigned& r0, unsigned& r1, unsigned& r2, unsigned& r3, unsigned addr) {
    asm volatile("ldmatrix.sync.aligned.m8n8.x4.trans.shared.b16 {%0,%1,%2,%3}, [%4];"
        : "=r"(r0), "=r"(r1), "=r"(r2), "=r"(r3) : "r"(addr));
}
__device__ __forceinline__ void mma16816(float* c, unsigned a0, unsigned a1, unsigned a2, unsigned a3,
                                         unsigned b0, unsigned b1) {
    asm volatile("mma.sync.aligned.m16n8k16.row.col.f32.bf16.bf16.f32 "
        "{%0,%1,%2,%3}, {%4,%5,%6,%7}, {%8,%9}, {%0,%1,%2,%3};"
        : "+f"(c[0]), "+f"(c[1]), "+f"(c[2]), "+f"(c[3])
        : "r"(a0), "r"(a1), "r"(a2), "r"(a3), "r"(b0), "r"(b1));
}
__device__ __forceinline__ void bf16split(float x, __nv_bfloat16& h, __nv_bfloat16& l) {
    h = __float2bfloat16(x);
    l = __float2bfloat16(x - __bfloat162float(h));
}
__device__ __forceinline__ void cp16(unsigned dst, const void* src) {
    asm volatile("cp.async.cg.shared.global [%0], [%1], 16;" :: "r"(dst), "l"(src));
}
#define CP_COMMIT() asm volatile("cp.async.commit_group;" ::: "memory")
#define CP_WAIT1()  asm volatile("cp.async.wait_group 1;"  ::: "memory")

// ---------------- scratch (static device globals; all bf16 hi/lo pairs) ----------------
__device__ __nv_bfloat16 g_XH[NB*SEQ*DM], g_XL[NB*SEQ*DM];   // sequence
__device__ __nv_bfloat16 g_WH[4*DM*DM],  g_WL[4*DM*DM];      // Wq,Wk,Wv,Wo
__device__ __nv_bfloat16 g_QH[GHD*SEQ*HD], g_QL[GHD*SEQ*HD];
__device__ __nv_bfloat16 g_KH[GHD*SEQ*HD], g_KL[GHD*SEQ*HD];
__device__ __nv_bfloat16 g_VH[GHD*SEQ*HD], g_VL[GHD*SEQ*HD];
__device__ __nv_bfloat16 g_AH[NB*SEQ*DM],  g_AL[NB*SEQ*DM];  // attended

// ================= xPos rotary helper =================
__device__ __forceinline__ void rope_pair(float& x1, float& x2, int deven, float pf, bool down)
{
    float sv   = ((float)deven + 25.6f) * (1.0f / 89.6f);
    float invf = powf(10000.0f, -(float)deven * (1.0f / 64.0f));
    float th   = pf * invf;
    float sn, cs;
    sincosf(th, &sn, &cs);
    float sc = powf(sv, pf * (1.0f / 512.0f));
    if (down) sc = 1.0f / sc;
    float y1 = (x1 * cs - x2 * sn) * sc;
    float y2 = (x2 * cs + x1 * sn) * sc;
    x1 = y1; x2 = y2;
}

// ================= Kernel 0: one-shot fp32 -> bf16 hi/lo conversion =================
#define X_F4 ((NB*SEQ*DM)/4)     /* 524288 */
#define W_F4 ((DM*DM)/4)         /* 65536 = 2^16 */

__global__ __launch_bounds__(256) void convert_kernel(
    const float* __restrict__ X,
    const float* __restrict__ Wq, const float* __restrict__ Wk,
    const float* __restrict__ Wv, const float* __restrict__ Wo)
{
    int gid = blockIdx.x * 256 + threadIdx.x;          // float4 index
    const float* src; __nv_bfloat16 *dh, *dl; int off;
    if (gid < X_F4) {
        src = X; dh = g_XH; dl = g_XL; off = gid;
    } else {
        int t = gid - X_F4;
        int w = t >> 16;                // 65536 float4 per weight
        off   = t & (W_F4 - 1);
        src = (w == 0) ? Wq : (w == 1) ? Wk : (w == 2) ? Wv : Wo;
        dh = g_WH + w * DM * DM; dl = g_WL + w * DM * DM;
    }
    float4 v = ((const float4*)src)[off];
    __nv_bfloat16 h0,h1,h2,h3,l0,l1,l2,l3;
    bf16split(v.x,h0,l0); bf16split(v.y,h1,l1); bf16split(v.z,h2,l2); bf16split(v.w,h3,l3);
    __nv_bfloat162* ph = (__nv_bfloat162*)(dh + off * 4);
    __nv_bfloat162* pl = (__nv_bfloat162*)(dl + off * 4);
    ph[0] = __halves2bfloat162(h0,h1); ph[1] = __halves2bfloat162(h2,h3);
    pl[0] = __halves2bfloat162(l0,l1); pl[1] = __halves2bfloat162(l2,l3);
}

// B-pair ldsm4 lane offset (bytes): n-tile pair, K-major smem stride 144 B
#define BOFF4(lane) ((unsigned)((((lane) & 7) + (((lane) >> 4) * 8)) * 144 + ((((lane) >> 3) & 1) * 16)))

// ================= Kernel 1: QKV projection via 3-pass bf16-split MMA =================
__global__ __launch_bounds__(256) void qkv_mma(
    const float* __restrict__ bq, const float* __restrict__ bk, const float* __restrict__ bv,
    const int* __restrict__ positions)
{
    __shared__ __nv_bfloat16 XHs[64*72], XLs[64*72], WHs[64*72], WLs[64*72];

    const int tid  = threadIdx.x;
    const int warp = tid >> 5;
    const int lane = tid & 31;
    const int wr   = (warp >> 1) * 16;
    const int wc   = (warp & 1) * 32;
    const int r0   = blockIdx.x * 64;
    const int c0   = blockIdx.y * 64;
    const int kind = c0 / DM;
    const int cW   = c0 % DM;
    const int h    = cW >> 6;

    const __nv_bfloat16* WHg = g_WH + (size_t)kind * DM * DM;
    const __nv_bfloat16* WLg = g_WL + (size_t)kind * DM * DM;

    const unsigned sXH = (unsigned)__cvta_generic_to_shared(XHs);
    const unsigned sXL = (unsigned)__cvta_generic_to_shared(XLs);
    const unsigned sWH = (unsigned)__cvta_generic_to_shared(WHs);
    const unsigned sWL = (unsigned)__cvta_generic_to_shared(WLs);

    float o[4][4];
    #pragma unroll
    for (int n = 0; n < 4; ++n)
        #pragma unroll
        for (int r = 0; r < 4; ++r) o[n][r] = 0.0f;

    const unsigned aoffA = (unsigned)((lane & 15) * 72 + (lane >> 4) * 8);
    const unsigned boff4 = BOFF4(lane);

    for (int kb = 0; kb < DM; kb += 64) {
        for (int it = tid; it < 512; it += 256) {
            int rr = it >> 3, f8 = (it & 7) * 8;
            *(uint4*)&XHs[rr*72 + f8] = *(const uint4*)&g_XH[(size_t)(r0+rr)*DM + kb + f8];
            *(uint4*)&XLs[rr*72 + f8] = *(const uint4*)&g_XL[(size_t)(r0+rr)*DM + kb + f8];
            *(uint4*)&WHs[rr*72 + f8] = *(const uint4*)&WHg[(size_t)(cW+rr)*DM + kb + f8];
            *(uint4*)&WLs[rr*72 + f8] = *(const uint4*)&WLg[(size_t)(cW+rr)*DM + kb + f8];
        }
        __syncthreads();

        #pragma unroll
        for (int kt = 0; kt < 4; ++kt) {
            unsigned aH0,aH1,aH2,aH3, aL0,aL1,aL2,aL3;
            unsigned abase = (aoffA + (unsigned)(kt * 16)) * 2u + (unsigned)(wr * 144);
            ldsm4(aH0,aH1,aH2,aH3, sXH + abase);
            ldsm4(aL0,aL1,aL2,aL3, sXL + abase);
            #pragma unroll
            for (int np = 0; np < 4; np += 2) {
                unsigned bH0,bH1,bH2,bH3, bL0,bL1,bL2,bL3;
                unsigned bbase = boff4 + (unsigned)((wc + np * 8) * 144) + (unsigned)(kt * 32);
                ldsm4(bH0,bH1,bH2,bH3, sWH + bbase);
                ldsm4(bL0,bL1,bL2,bL3, sWL + bbase);
                mma16816(o[np],   aH0,aH1,aH2,aH3, bH0,bH1);
                mma16816(o[np],   aL0,aL1,aL2,aL3, bH0,bH1);
                mma16816(o[np],   aH0,aH1,aH2,aH3, bL0,bL1);
                mma16816(o[np+1], aH0,aH1,aH2,aH3, bH2,bH3);
                mma16816(o[np+1], aL0,aL1,aL2,aL3, bH2,bH3);
                mma16816(o[np+1], aH0,aH1,aH2,aH3, bL2,bL3);
            }
        }
        __syncthreads();
    }

    const int lrow = wr + (lane >> 2);
    const int rA = r0 + lrow, rB = rA + 8;
    const int nA = rA >> 11, sA = rA & 2047;
    const int nBt = rB >> 11, sB = rB & 2047;
    const float* bias = (kind == 0) ? bq : (kind == 1) ? bk : bv;
    __nv_bfloat16* OH = (kind == 0) ? g_QH : (kind == 1) ? g_KH : g_VH;
    __nv_bfloat16* OL = (kind == 0) ? g_QL : (kind == 1) ? g_KL : g_VL;
    const size_t baseA = ((size_t)(nA  * NH + h) * SEQ + sA) * HD;
    const size_t baseB = ((size_t)(nBt * NH + h) * SEQ + sB) * HD;
    float pfA = 0.f, pfB = 0.f;
    if (kind != 2) { pfA = (float)positions[rA]; pfB = (float)positions[rB]; }

    #pragma unroll
    for (int n = 0; n < 4; ++n) {
        int d0 = wc + n * 8 + (lane & 3) * 2;
        float b0 = bias[cW + d0], b1 = bias[cW + d0 + 1];
        float vA0 = o[n][0] + b0, vA1 = o[n][1] + b1;
        float vB0 = o[n][2] + b0, vB1 = o[n][3] + b1;
        if (kind != 2) {
            if (kind == 0) { vA0 *= 0.125f; vA1 *= 0.125f; vB0 *= 0.125f; vB1 *= 0.125f; }
            bool down = (kind == 1);
            rope_pair(vA0, vA1, d0, pfA, down);
            rope_pair(vB0, vB1, d0, pfB, down);
        }
        __nv_bfloat16 h0,h1,l0,l1;
        bf16split(vA0,h0,l0); bf16split(vA1,h1,l1);
        *(__nv_bfloat162*)&OH[baseA + d0] = __halves2bfloat162(h0,h1);
        *(__nv_bfloat162*)&OL[baseA + d0] = __halves2bfloat162(l0,l1);
        bf16split(vB0,h0,l0); bf16split(vB1,h1,l1);
        *(__nv_bfloat162*)&OH[baseB + d0] = __halves2bfloat162(h0,h1);
        *(__nv_bfloat162*)&OL[baseB + d0] = __halves2bfloat162(l0,l1);
    }
}

// ================= Kernel 2: tensor-core attention =================
#define SO_QH   0
#define SO_QL   9216
#define SO_K0   18432            /* KH buf0; KL at +9216 */
#define SO_K1   36864            /* KH buf1; KL at +9216 */
#define SO_VH   55296            /* V row-major [t][d], stride 72 */
#define SO_VL   64512
#define SO_WHo  73728            /* weights bf16 hi, [row][col] stride 72 */
#define SO_WLo  82944
#define SO_AS   92160            /* fp32 sigmoid A, [row][col] stride 68 */
#define SO_WB   109568           /* fp32 [64] boundary weights */
#define SO_MS   109824           /* fp32 [64] mask tile */
#define ATTN_SMEM 110080

__global__ __launch_bounds__(256, 2) void attn_kernel(const float* __restrict__ mask)
{
    extern __shared__ char smc[];
    __nv_bfloat16* QH  = (__nv_bfloat16*)(smc + SO_QH);
    __nv_bfloat16* QL  = (__nv_bfloat16*)(smc + SO_QL);
    __nv_bfloat16* WHs = (__nv_bfloat16*)(smc + SO_WHo);
    __nv_bfloat16* WLs = (__nv_bfloat16*)(smc + SO_WLo);
    float* AS  = (float*)(smc + SO_AS);
    float* WB  = (float*)(smc + SO_WB);
    float* MS  = (float*)(smc + SO_MS);

    const unsigned sb = (unsigned)__cvta_generic_to_shared(smc);

    const int tid  = threadIdx.x;
    const int warp = tid >> 5;
    const int lane = tid & 31;
    const int wr   = (warp >> 1) * 16;
    const int wc   = (warp & 1) * 32;
    const int gh   = blockIdx.y;
    const int nb   = gh >> 3;
    const int hh   = gh & 7;
    const int rb   = (int)(gridDim.x - 1 - blockIdx.x);   // heavy blocks first
    const int s0   = rb * 64;

    const __nv_bfloat16* QHg = g_QH + (size_t)gh * SEQ * HD;
    const __nv_bfloat16* QLg = g_QL + (size_t)gh * SEQ * HD;
    const __nv_bfloat16* KHg = g_KH + (size_t)gh * SEQ * HD;
    const __nv_bfloat16* KLg = g_KL + (size_t)gh * SEQ * HD;
    const __nv_bfloat16* VHg = g_VH + (size_t)gh * SEQ * HD;
    const __nv_bfloat16* VLg = g_VL + (size_t)gh * SEQ * HD;

    // ---- copy Q tile (sync, once) ----
    for (int it = tid; it < 512; it += 256) {
        int rr = it >> 3, f8 = (it & 7) * 8;
        *(uint4*)&QH[rr*72 + f8] = *(const uint4*)&QHg[(size_t)(s0+rr)*HD + f8];
        *(uint4*)&QL[rr*72 + f8] = *(const uint4*)&QLg[(size_t)(s0+rr)*HD + f8];
    }

    // ---- prefetch K(rb) into buf0 ----
    {
        const int lo0 = rb * 64;
        #pragma unroll
        for (int q = 0; q < 2; ++q) {
            int it = tid + q * 256;
            int rr = it >> 3, f8 = (it & 7) * 8;
            unsigned d = (unsigned)SO_K0 + (unsigned)((rr * 72 + f8) * 2);
            cp16(sb + d,        &KHg[(size_t)(lo0 + rr) * HD + f8]);
            cp16(sb + d + 9216, &KLg[(size_t)(lo0 + rr) * HD + f8]);
        }
    }
    CP_COMMIT();

    float cA = 0.0f;
    float cP = 1.0f;

    float o[4][4];
    #pragma unroll
    for (int n = 0; n < 4; ++n)
        #pragma unroll
        for (int r = 0; r < 4; ++r) o[n][r] = 0.0f;

    const unsigned aoffA = (unsigned)((lane & 15) * 72 + (lane >> 4) * 8);
    const unsigned boff4 = BOFF4(lane);
    const unsigned toff4 = (unsigned)((lane & 15) * 144 + (lane >> 4) * 16);   // trans-V n-pair

    for (int jb = rb; jb >= 0; --jb) {
        const int lo = jb * 64;
        const unsigned curK = ((rb - jb) & 1) ? (unsigned)SO_K1 : (unsigned)SO_K0;
        const unsigned nxtK = ((rb - jb) & 1) ? (unsigned)SO_K0 : (unsigned)SO_K1;

        // group A: V(jb) row-major + mask tile
        #pragma unroll
        for (int q = 0; q < 2; ++q) {
            int it = tid + q * 256;
            int rr = it >> 3, f8 = (it & 7) * 8;
            unsigned d = (unsigned)((rr * 72 + f8) * 2);
            cp16(sb + SO_VH + d, &VHg[(size_t)(lo + rr) * HD + f8]);
            cp16(sb + SO_VL + d, &VLg[(size_t)(lo + rr) * HD + f8]);
        }
        if (tid < 16) cp16(sb + SO_MS + (unsigned)(tid * 16), &mask[(size_t)nb * SEQ + lo + tid * 4]);
        CP_COMMIT();
        // group B: K(jb-1) into alternate buffer
        if (jb > 0) {
            #pragma unroll
            for (int q = 0; q < 2; ++q) {
                int it = tid + q * 256;
                int rr = it >> 3, f8 = (it & 7) * 8;
                unsigned d = nxtK + (unsigned)((rr * 72 + f8) * 2);
                cp16(sb + d,        &KHg[(size_t)(lo - 64 + rr) * HD + f8]);
                cp16(sb + d + 9216, &KLg[(size_t)(lo - 64 + rr) * HD + f8]);
            }
        }
        CP_COMMIT();
        CP_WAIT1();
        __syncthreads();            // (a)

        // ---- S = Q K^T via 3-pass bf16 split MMA (paired B ldsm4) ----
        float sc[4][4];
        #pragma unroll
        for (int n = 0; n < 4; ++n)
            #pragma unroll
            for (int r = 0; r < 4; ++r) sc[n][r] = 0.0f;

        #pragma unroll
        for (int kt = 0; kt < 4; ++kt) {
            unsigned aH0,aH1,aH2,aH3, aL0,aL1,aL2,aL3;
            unsigned abase = (aoffA + (unsigned)(kt * 16)) * 2u;
            ldsm4(aH0,aH1,aH2,aH3, sb + SO_QH + (unsigned)(wr * 144) + abase);
            ldsm4(aL0,aL1,aL2,aL3, sb + SO_QL + (unsigned)(wr * 144) + abase);
            #pragma unroll
            for (int np = 0; np < 4; np += 2) {
                unsigned bH0,bH1,bH2,bH3, bL0,bL1,bL2,bL3;
                unsigned bbase = boff4 + (unsigned)((wc + np * 8) * 144) + (unsigned)(kt * 32);
                ldsm4(bH0,bH1,bH2,bH3, sb + curK + bbase);
                ldsm4(bL0,bL1,bL2,bL3, sb + curK + 9216u + bbase);
                mma16816(sc[np],   aH0,aH1,aH2,aH3, bH0,bH1);
                mma16816(sc[np],   aL0,aL1,aL2,aL3, bH0,bH1);
                mma16816(sc[np],   aH0,aH1,aH2,aH3, bL0,bL1);
                mma16816(sc[np+1], aH0,aH1,aH2,aH3, bH2,bH3);
                mma16816(sc[np+1], aL0,aL1,aL2,aL3, bH2,bH3);
                mma16816(sc[np+1], aH0,aH1,aH2,aH3, bL2,bL3);
            }
        }

        // ---- sigmoid * mask * causal on fragments -> AS[row][col] ----
        {
            const int lrow = wr + (lane >> 2);
            #pragma unroll
            for (int n = 0; n < 4; ++n) {
                const int lc = wc + n * 8 + (lane & 3) * 2;
                float m0 = MS[lc], m1 = MS[lc + 1];
                float a0 = 0.f, a1 = 0.f, a2 = 0.f, a3 = 0.f;
                if (lo + lc     <= s0 + lrow)     a0 = __fdividef(m0, 1.0f + __expf(-sc[n][0]));
                if (lo + lc + 1 <= s0 + lrow)     a1 = __fdividef(m1, 1.0f + __expf(-sc[n][1]));
                if (lo + lc     <= s0 + lrow + 8) a2 = __fdividef(m0, 1.0f + __expf(-sc[n][2]));
                if (lo + lc + 1 <= s0 + lrow + 8) a3 = __fdividef(m1, 1.0f + __expf(-sc[n][3]));
                *(float2*)&AS[lrow * 68 + lc]       = make_float2(a0, a1);
                *(float2*)&AS[(lrow + 8) * 68 + lc] = make_float2(a2, a3);
            }
        }
        __syncthreads();            // (b)

        // ---- per-row serial suffix-product scan, float4-batched ----
        if (tid < 64) {
            const int r = tid;
            float lA = cA, lP = cP;
            #pragma unroll
            for (int cc = 60; cc >= 0; cc -= 4) {
                float4 a4 = *(const float4*)&AS[r * 68 + cc];
                {   float Pn = ((1.0f - a4.w) + EPSV) * lP; float w = lA * Pn;
                    if (cc == 60) WB[r] = w;
                    else { __nv_bfloat16 h,l; bf16split(w,h,l); WHs[r*72+cc+4]=h; WLs[r*72+cc+4]=l; }
                    lA = a4.w; lP = Pn; }
                {   float Pn = ((1.0f - a4.z) + EPSV) * lP; float w = lA * Pn;
                    __nv_bfloat16 h,l; bf16split(w,h,l); WHs[r*72+cc+3]=h; WLs[r*72+cc+3]=l;
                    lA = a4.z; lP = Pn; }
                {   float Pn = ((1.0f - a4.y) + EPSV) * lP; float w = lA * Pn;
                    __nv_bfloat16 h,l; bf16split(w,h,l); WHs[r*72+cc+2]=h; WLs[r*72+cc+2]=l;
                    lA = a4.y; lP = Pn; }
                {   float Pn = ((1.0f - a4.x) + EPSV) * lP; float w = lA * Pn;
                    __nv_bfloat16 h,l; bf16split(w,h,l); WHs[r*72+cc+1]=h; WLs[r*72+cc+1]=l;
                    lA = a4.x; lP = Pn; }
            }
            float w0 = (jb == 0) ? lA : 0.0f;
            __nv_bfloat16 h, l; bf16split(w0, h, l);
            WHs[r * 72] = h; WLs[r * 72] = l;
            cA = lA; cP = lP;
        }
        __syncthreads();            // (c)

        // ---- out += W * V via 3-pass bf16 split MMA (paired trans ldsm4) ----
        #pragma unroll
        for (int kt = 0; kt < 4; ++kt) {
            unsigned aH0,aH1,aH2,aH3, aL0,aL1,aL2,aL3;
            unsigned abase = (aoffA + (unsigned)(kt * 16)) * 2u;
            ldsm4(aH0,aH1,aH2,aH3, sb + SO_WHo + (unsigned)(wr * 144) + abase);
            ldsm4(aL0,aL1,aL2,aL3, sb + SO_WLo + (unsigned)(wr * 144) + abase);
            unsigned tb = (unsigned)(kt * 16 * 144) + toff4;
            #pragma unroll
            for (int np = 0; np < 4; np += 2) {
                unsigned bH0,bH1,bH2,bH3, bL0,bL1,bL2,bL3;
                unsigned bbase = tb + (unsigned)((wc + np * 8) * 2);
                ldsm4t(bH0,bH1,bH2,bH3, sb + SO_VH + bbase);
                ldsm4t(bL0,bL1,bL2,bL3, sb + SO_VL + bbase);
                mma16816(o[np],   aH0,aH1,aH2,aH3, bH0,bH1);
                mma16816(o[np],   aL0,aL1,aL2,aL3, bH0,bH1);
                mma16816(o[np],   aH0,aH1,aH2,aH3, bL0,bL1);
                mma16816(o[np+1], aH0,aH1,aH2,aH3, bH2,bH3);
                mma16816(o[np+1], aL0,aL1,aL2,aL3, bH2,bH3);
                mma16816(o[np+1], aH0,aH1,aH2,aH3, bL2,bL3);
            }
        }
        // boundary column: WB x V row lo+64
        if (jb < rb) {
            size_t vb = (size_t)(lo + 64) * HD;
            float wb0 = WB[wr + (lane >> 2)];
            float wb1 = WB[wr + (lane >> 2) + 8];
            #pragma unroll
            for (int n = 0; n < 4; ++n) {
                int d0 = wc + n * 8 + (lane & 3) * 2;
                __nv_bfloat162 hp = *(const __nv_bfloat162*)&VHg[vb + d0];
                __nv_bfloat162 lp = *(const __nv_bfloat162*)&VLg[vb + d0];
                float v0 = __bfloat162float(hp.x) + __bfloat162float(lp.x);
                float v1 = __bfloat162float(hp.y) + __bfloat162float(lp.y);
                o[n][0] = fmaf(wb0, v0, o[n][0]);
                o[n][1] = fmaf(wb0, v1, o[n][1]);
                o[n][2] = fmaf(wb1, v0, o[n][2]);
                o[n][3] = fmaf(wb1, v1, o[n][3]);
            }
        }
        __syncthreads();            // (d)
    }

    // ---- write attended fragments as bf16 hi/lo ----
    {
        const int lrow = wr + (lane >> 2);
        #pragma unroll
        for (int n = 0; n < 4; ++n) {
            const int d0 = wc + n * 8 + (lane & 3) * 2;
            size_t bA = ((size_t)(nb * SEQ + s0 + lrow)) * DM + hh * HD + d0;
            size_t bB = ((size_t)(nb * SEQ + s0 + lrow + 8)) * DM + hh * HD + d0;
            __nv_bfloat16 h0,h1,l0,l1;
            bf16split(o[n][0],h0,l0); bf16split(o[n][1],h1,l1);
            *(__nv_bfloat162*)&g_AH[bA] = __halves2bfloat162(h0,h1);
            *(__nv_bfloat162*)&g_AL[bA] = __halves2bfloat162(l0,l1);
            bf16split(o[n][2],h0,l0); bf16split(o[n][3],h1,l1);
            *(__nv_bfloat162*)&g_AH[bB] = __halves2bfloat162(h0,h1);
            *(__nv_bfloat162*)&g_AL[bB] = __halves2bfloat162(l0,l1);
        }
    }
}

// ================= Kernel 3: output projection via 3-pass bf16-split MMA =================
__global__ __launch_bounds__(256) void oproj_mma(
    const float* __restrict__ bo, float* __restrict__ outp)
{
    __shared__ __nv_bfloat16 XHs[64*72], XLs[64*72], WHs[64*72], WLs[64*72];

    const int tid  = threadIdx.x;
    const int warp = tid >> 5;
    const int lane = tid & 31;
    const int wr   = (warp >> 1) * 16;
    const int wc   = (warp & 1) * 32;
    const int r0   = blockIdx.x * 64;
    const int c0   = blockIdx.y * 64;

    const __nv_bfloat16* WHg = g_WH + (size_t)3 * DM * DM;
    const __nv_bfloat16* WLg = g_WL + (size_t)3 * DM * DM;

    const unsigned sXH = (unsigned)__cvta_generic_to_shared(XHs);
    const unsigned sXL = (unsigned)__cvta_generic_to_shared(XLs);
    const unsigned sWH = (unsigned)__cvta_generic_to_shared(WHs);
    const unsigned sWL = (unsigned)__cvta_generic_to_shared(WLs);

    float o[4][4];
    #pragma unroll
    for (int n = 0; n < 4; ++n)
        #pragma unroll
        for (int r = 0; r < 4; ++r) o[n][r] = 0.0f;

    const unsigned aoffA = (unsigned)((lane & 15) * 72 + (lane >> 4) * 8);
    const unsigned boff4 = BOFF4(lane);

    for (int kb = 0; kb < DM; kb += 64) {
        for (int it = tid; it < 512; it += 256) {
            int rr = it >> 3, f8 = (it & 7) * 8;
            *(uint4*)&XHs[rr*72 + f8] = *(const uint4*)&g_AH[(size_t)(r0+rr)*DM + kb + f8];
            *(uint4*)&XLs[rr*72 + f8] = *(const uint4*)&g_AL[(size_t)(r0+rr)*DM + kb + f8];
            *(uint4*)&WHs[rr*72 + f8] = *(const uint4*)&WHg[(size_t)(c0+rr)*DM + kb + f8];
            *(uint4*)&WLs[rr*72 + f8] = *(const uint4*)&WLg[(size_t)(c0+rr)*DM + kb + f8];
        }
        __syncthreads();

        #pragma unroll
        for (int kt = 0; kt < 4; ++kt) {
            unsigned aH0,aH1,aH2,aH3, aL0,aL1,aL2,aL3;
            unsigned abase = (aoffA + (unsigned)(kt * 16)) * 2u + (unsigned)(wr * 144);
            ldsm4(aH0,aH1,aH2,aH3, sXH + abase);
            ldsm4(aL0,aL1,aL2,aL3, sXL + abase);
            #pragma unroll
            for (int np = 0; np < 4; np += 2) {
                unsigned bH0,bH1,bH2,bH3, bL0,bL1,bL2,bL3;
                unsigned bbase = boff4 + (unsigned)((wc + np * 8) * 144) + (unsigned)(kt * 32);
                ldsm4(bH0,bH1,bH2,bH3, sWH + bbase);
                ldsm4(bL0,bL1,bL2,bL3, sWL + bbase);
                mma16816(o[np],   aH0,aH1,aH2,aH3, bH0,bH1);
                mma16816(o[np],   aL0,aL1,aL2,aL3, bH0,bH1);
                mma16816(o[np],   aH0,aH1,aH2,aH3, bL0,bL1);
                mma16816(o[np+1], aH0,aH1,aH2,aH3, bH2,bH3);
                mma16816(o[np+1], aL0,aL1,aL2,aL3, bH2,bH3);
                mma16816(o[np+1], aH0,aH1,aH2,aH3, bL2,bL3);
            }
        }
        __syncthreads();
    }

    const int lrow = wr + (lane >> 2);
    const int rA = r0 + lrow, rB = rA + 8;
    #pragma unroll
    for (int n = 0; n < 4; ++n) {
        int d0 = wc + n * 8 + (lane & 3) * 2;
        float b0 = bo[c0 + d0], b1 = bo[c0 + d0 + 1];
        *(float2*)&outp[(size_t)rA * DM + c0 + d0] = make_float2(o[n][0] + b0, o[n][1] + b1);
        *(float2*)&outp[(size_t)rB * DM + c0 + d0] = make_float2(o[n][2] + b0, o[n][3] + b1);
    }
}

// ================= host launcher =================
extern "C" void kernel_launch(void* const* d_in, const int* in_sizes, int n_in,
                              void* d_out, int out_size)
{
    const float* seqp = nullptr;
    const float* maskp = nullptr;
    const int*   posp = nullptr;
    const float* W[4] = {nullptr, nullptr, nullptr, nullptr};
    const float* B[4] = {nullptr, nullptr, nullptr, nullptr};
    int nw = 0, nbb = 0, n4096 = 0;
    for (int i = 0; i < n_in; ++i) {
        int sz = in_sizes[i];
        if (sz == NB * SEQ * DM) {
            seqp = (const float*)d_in[i];
        } else if (sz == DM * DM) {
            if (nw < 4) W[nw++] = (const float*)d_in[i];
        } else if (sz == DM) {
            if (nbb < 4) B[nbb++] = (const float*)d_in[i];
        } else if (sz == NB * SEQ) {
            if (n4096 == 0) maskp = (const float*)d_in[i];
            else            posp  = (const int*)d_in[i];
            ++n4096;
        }
    }

    cudaFuncSetAttribute(attn_kernel, cudaFuncAttributeMaxDynamicSharedMemorySize, ATTN_SMEM);

    convert_kernel<<<(X_F4 + 4 * W_F4) / 256, 256>>>(seqp, W[0], W[1], W[2], W[3]);
    qkv_mma<<<dim3(64, 24), 256>>>(B[0], B[1], B[2], posp);
    attn_kernel<<<dim3(32, 16), 256, ATTN_SMEM>>>(maskp);
    oproj_mma<<<dim3(64, 8), 256>>>(B[3], (float*)d_out);
}